// round 4
// baseline (speedup 1.0000x reference)
#include <cuda_runtime.h>
#include <cstdint>

#define NN 50000
#define HD 128
#define EE 640000
#define GG 128

typedef unsigned int u32;

// Scratch ping-pong buffers (25.6 MB each)
__device__ float g_bufA[NN * HD];
__device__ float g_bufB[NN * HD];
__device__ float g_bufC[NN * HD];

__device__ __forceinline__ float tf32hi(float a) {
    u32 r;
    asm("cvt.rna.tf32.f32 %0, %1;" : "=r"(r) : "f"(a));
    return __uint_as_float(r);
}

__device__ __forceinline__ void mma_tf32(float* d, const u32* a, const u32* b) {
    asm volatile(
        "mma.sync.aligned.m16n8k8.row.col.f32.tf32.tf32.f32 "
        "{%0,%1,%2,%3}, {%4,%5,%6,%7}, {%8,%9}, {%0,%1,%2,%3};"
        : "+f"(d[0]), "+f"(d[1]), "+f"(d[2]), "+f"(d[3])
        : "r"(a[0]), "r"(a[1]), "r"(a[2]), "r"(a[3]), "r"(b[0]), "r"(b[1]));
}

// ---------------------------------------------------------------------------
// Dynamic smem layout (bytes). W stored transposed [n][k], stride 132 floats;
// A chunk [m][k(32)], stride 36 floats. Both give conflict-free fragment LDS.
// ---------------------------------------------------------------------------
#define WS 132
#define AS 36
#define SM_BB   0
#define SM_SC   512
#define SM_OF   1024
#define SM_WHI  1536
#define SM_WLO  (SM_WHI + 128 * WS * 4)
#define SM_AHI  (SM_WLO + 128 * WS * 4)
#define SM_ALO  (SM_AHI + 128 * AS * 4)
#define SM_TOT  (SM_ALO + 128 * AS * 4)   // 173568 B

// ---------------------------------------------------------------------------
// Split-TF32 GEMM via mma.sync (m16n8k8): out[M,128] = epi(A@W + bias).
// epi = relu [+BN folded to t*sc+of]. Optional dual write.
// Block 128x128, 8 warps, warp tile 32x64 (2 m-tiles x 8 n-tiles).
// 3xTF32: d += Ahi*Whi + Ahi*Wlo + Alo*Whi.
// ---------------------------------------------------------------------------
template <bool DO_BN, bool DUAL>
__global__ void __launch_bounds__(256, 1) gemm_tc(
    const float* __restrict__ A, const float* __restrict__ W,
    const float* __restrict__ bias, const float* __restrict__ gam,
    const float* __restrict__ bet, const float* __restrict__ mmean,
    const float* __restrict__ mvar,
    float* __restrict__ out, float* __restrict__ out2, int M)
{
    extern __shared__ char sm[];
    float* const bb  = (float*)(sm + SM_BB);
    float* const sc  = (float*)(sm + SM_SC);
    float* const of  = (float*)(sm + SM_OF);
    float* const whi = (float*)(sm + SM_WHI);
    float* const wlo = (float*)(sm + SM_WLO);
    float* const ahi = (float*)(sm + SM_AHI);
    float* const alo = (float*)(sm + SM_ALO);

    const int tid = threadIdx.x, wid = tid >> 5, lane = tid & 31;
    const int g = lane >> 2, q = lane & 3;
    const int wm = wid & 3, wn = wid >> 2;       // warp row/col group
    const int row0 = blockIdx.x * 128;

    // Epilogue params
    if (tid < 128) {
        bb[tid] = bias[tid];
        float s = 1.f, o = 0.f;
        if (DO_BN) {
            s = gam[tid] * rsqrtf(mvar[tid] + 1e-3f);
            o = bet[tid] - mmean[tid] * s;
        }
        sc[tid] = s;
        of[tid] = o;
    }

    // Preload W transposed into [n][k] hi/lo.
#pragma unroll
    for (int i = 0; i < 16; i++) {
        int idx = tid + i * 256;                 // 4096 float4 slots
        int k = idx >> 5;                        // 0..127
        int nq = idx & 31;
        float4 v = *(const float4*)(W + (size_t)k * HD + nq * 4);
        float vv[4] = { v.x, v.y, v.z, v.w };
#pragma unroll
        for (int j = 0; j < 4; j++) {
            int n = nq * 4 + j;
            float hi = tf32hi(vv[j]);
            whi[n * WS + k] = hi;
            wlo[n * WS + k] = vv[j] - hi;
        }
    }

    float d[2][8][4];
#pragma unroll
    for (int mt = 0; mt < 2; mt++)
#pragma unroll
        for (int nt = 0; nt < 8; nt++)
#pragma unroll
            for (int c = 0; c < 4; c++) d[mt][nt][c] = 0.f;

#pragma unroll 1
    for (int ch = 0; ch < 4; ++ch) {
        __syncthreads();
        // Load A chunk (128 rows x 32 k), split hi/lo.
#pragma unroll
        for (int i = 0; i < 4; i++) {
            int idx = tid + i * 256;             // 1024 float4 slots
            int r = idx >> 3;                    // 0..127
            int kq = idx & 7;
            int grow = row0 + r;
            float4 v = make_float4(0.f, 0.f, 0.f, 0.f);
            if (grow < M)
                v = *(const float4*)(A + (size_t)grow * HD + ch * 32 + kq * 4);
            float h0 = tf32hi(v.x), h1 = tf32hi(v.y),
                  h2 = tf32hi(v.z), h3 = tf32hi(v.w);
            *(float4*)&ahi[r * AS + kq * 4] = make_float4(h0, h1, h2, h3);
            *(float4*)&alo[r * AS + kq * 4] =
                make_float4(v.x - h0, v.y - h1, v.z - h2, v.w - h3);
        }
        __syncthreads();

#pragma unroll
        for (int ks = 0; ks < 4; ++ks) {
            const int kl = ks * 8;               // chunk-local k
            const int kw = ch * 32 + kl;         // global k (for W)
            u32 fa_hi[2][4], fa_lo[2][4];
#pragma unroll
            for (int mt = 0; mt < 2; mt++) {
                int rm = wm * 32 + mt * 16;
                const float* ph = &ahi[(rm + g) * AS + kl + q];
                const float* pl = &alo[(rm + g) * AS + kl + q];
                fa_hi[mt][0] = __float_as_uint(ph[0]);
                fa_hi[mt][1] = __float_as_uint(ph[8 * AS]);
                fa_hi[mt][2] = __float_as_uint(ph[4]);
                fa_hi[mt][3] = __float_as_uint(ph[8 * AS + 4]);
                fa_lo[mt][0] = __float_as_uint(pl[0]);
                fa_lo[mt][1] = __float_as_uint(pl[8 * AS]);
                fa_lo[mt][2] = __float_as_uint(pl[4]);
                fa_lo[mt][3] = __float_as_uint(pl[8 * AS + 4]);
            }
            u32 fb_hi[8][2], fb_lo[8][2];
#pragma unroll
            for (int nt = 0; nt < 8; nt++) {
                int nb = wn * 64 + nt * 8;
                const float* ph = &whi[(nb + g) * WS + kw + q];
                const float* pl = &wlo[(nb + g) * WS + kw + q];
                fb_hi[nt][0] = __float_as_uint(ph[0]);
                fb_hi[nt][1] = __float_as_uint(ph[4]);
                fb_lo[nt][0] = __float_as_uint(pl[0]);
                fb_lo[nt][1] = __float_as_uint(pl[4]);
            }
#pragma unroll
            for (int mt = 0; mt < 2; mt++)
#pragma unroll
                for (int nt = 0; nt < 8; nt++) {
                    mma_tf32(d[mt][nt], fa_hi[mt], fb_hi[nt]);
                    mma_tf32(d[mt][nt], fa_hi[mt], fb_lo[nt]);
                    mma_tf32(d[mt][nt], fa_lo[mt], fb_hi[nt]);
                }
        }
    }

    // Epilogue: c0/c1 at (row g, col 2q/2q+1), c2/c3 at (row g+8, same cols)
    const int q2 = q * 2;
#pragma unroll
    for (int mt = 0; mt < 2; mt++) {
        int r0 = row0 + wm * 32 + mt * 16 + g;
#pragma unroll
        for (int nt = 0; nt < 8; nt++) {
            int col = wn * 64 + nt * 8 + q2;
            float s0 = sc[col], s1 = sc[col + 1];
            float o0 = of[col], o1 = of[col + 1];
            float B0 = bb[col], B1 = bb[col + 1];
            float v0 = fmaxf(d[mt][nt][0] + B0, 0.f) * s0 + o0;
            float v1 = fmaxf(d[mt][nt][1] + B1, 0.f) * s1 + o1;
            float v2 = fmaxf(d[mt][nt][2] + B0, 0.f) * s0 + o0;
            float v3 = fmaxf(d[mt][nt][3] + B1, 0.f) * s1 + o1;
            if (r0 < M) {
                *(float2*)(out + (size_t)r0 * HD + col) = make_float2(v0, v1);
                if (DUAL)
                    *(float2*)(out2 + (size_t)r0 * HD + col) = make_float2(v0, v1);
            }
            if (r0 + 8 < M) {
                *(float2*)(out + (size_t)(r0 + 8) * HD + col) = make_float2(v2, v3);
                if (DUAL)
                    *(float2*)(out2 + (size_t)(r0 + 8) * HD + col) = make_float2(v2, v3);
            }
        }
    }
}

// ---------------------------------------------------------------------------
// Edge scatter-add: out[dst,:] += h[src,:]. One warp per edge; one float4
// gather + one red.global.add.v4.f32 per lane. h is L2-resident.
// ---------------------------------------------------------------------------
__global__ void scatter_add(const float* __restrict__ h,
                            const int* __restrict__ ei,
                            float* __restrict__ out)
{
    int t = blockIdx.x * blockDim.x + threadIdx.x;
    if (t >= EE * 32) return;
    int e = t >> 5;
    int j = t & 31;
    int src = __ldg(ei + 2 * e);
    int dst = __ldg(ei + 2 * e + 1);
    float4 v = __ldg((const float4*)(h + (size_t)src * HD) + j);
    float4* o = (float4*)(out + (size_t)dst * HD) + j;
    asm volatile("red.global.add.v4.f32 [%0], {%1, %2, %3, %4};"
                 :: "l"(o), "f"(v.x), "f"(v.y), "f"(v.z), "f"(v.w)
                 : "memory");
}

// ---------------------------------------------------------------------------
// Final graph readout: out[batch[n],:] += h[n,:], batch sorted -> chunked
// register accumulation, one atomic per group boundary.
// ---------------------------------------------------------------------------
#define SEG_CH 64
__global__ void seg_sum(const float* __restrict__ h,
                        const int* __restrict__ batch,
                        float* __restrict__ out)
{
    int n0 = blockIdx.x * SEG_CH;
    if (n0 >= NN) return;
    int j = threadIdx.x;            // 0..127
    int nend = n0 + SEG_CH;
    if (nend > NN) nend = NN;
    float acc = 0.f;
    int cur = __ldg(batch + n0);
    for (int n = n0; n < nend; ++n) {
        int b = __ldg(batch + n);
        if (b != cur) {
            atomicAdd(out + (size_t)cur * HD + j, acc);
            acc = 0.f;
            cur = b;
        }
        acc += __ldg(h + (size_t)n * HD + j);
    }
    atomicAdd(out + (size_t)cur * HD + j, acc);
}

__global__ void zero_out(float* __restrict__ out, int n)
{
    int t = blockIdx.x * blockDim.x + threadIdx.x;
    if (t < n) out[t] = 0.f;
}

extern "C" void kernel_launch(void* const* d_in, const int* in_sizes, int n_in,
                              void* d_out, int out_size)
{
    const float* x   = (const float*)d_in[0];
    const int*   ei  = (const int*)d_in[1];
    const int*   bat = (const int*)d_in[2];
    const float* W1  = (const float*)d_in[3];
    const float* b1  = (const float*)d_in[4];
    const float* g1  = (const float*)d_in[5];
    const float* be1 = (const float*)d_in[6];
    const float* mm1 = (const float*)d_in[7];
    const float* mv1 = (const float*)d_in[8];
    const float* W2  = (const float*)d_in[9];
    const float* b2  = (const float*)d_in[10];
    const float* W3  = (const float*)d_in[11];
    const float* b3  = (const float*)d_in[12];
    const float* g2  = (const float*)d_in[13];
    const float* be2 = (const float*)d_in[14];
    const float* mm2 = (const float*)d_in[15];
    const float* mv2 = (const float*)d_in[16];
    const float* W4  = (const float*)d_in[17];
    const float* b4  = (const float*)d_in[18];
    float* out = (float*)d_out;

    float *bufA, *bufB, *bufC;
    cudaGetSymbolAddress((void**)&bufA, g_bufA);
    cudaGetSymbolAddress((void**)&bufB, g_bufB);
    cudaGetSymbolAddress((void**)&bufC, g_bufC);

    static bool attr_done = false;
    if (!attr_done) {
        cudaFuncSetAttribute(gemm_tc<true, false>,
                             cudaFuncAttributeMaxDynamicSharedMemorySize, SM_TOT);
        cudaFuncSetAttribute(gemm_tc<false, true>,
                             cudaFuncAttributeMaxDynamicSharedMemorySize, SM_TOT);
        cudaFuncSetAttribute(gemm_tc<true, true>,
                             cudaFuncAttributeMaxDynamicSharedMemorySize, SM_TOT);
        cudaFuncSetAttribute(gemm_tc<false, false>,
                             cudaFuncAttributeMaxDynamicSharedMemorySize, SM_TOT);
        attr_done = true;
    }

    const int gemm_blocks = (NN + 127) / 128;         // 391
    const int scat_blocks = (EE * 32 + 255) / 256;    // 80000
    const int seg_blocks  = (NN + SEG_CH - 1) / SEG_CH;

    // h = bn1(relu(x@W1+b1))
    gemm_tc<true, false><<<gemm_blocks, 256, SM_TOT>>>(
        x, W1, b1, g1, be1, mm1, mv1, bufA, nullptr, NN);
    // h = relu(h@W2+b2); bufB = h, bufC = h (agg accumulator init)
    gemm_tc<false, true><<<gemm_blocks, 256, SM_TOT>>>(
        bufA, W2, b2, nullptr, nullptr, nullptr, nullptr, bufB, bufC, NN);
    // bufC = h + segment_sum(h[src] -> dst)
    scatter_add<<<scat_blocks, 256>>>(bufB, ei, bufC);
    // h = bn2(relu(bufC@W3+b3)); bufA = h, bufB = h (agg accumulator init)
    gemm_tc<true, true><<<gemm_blocks, 256, SM_TOT>>>(
        bufC, W3, b3, g2, be2, mm2, mv2, bufA, bufB, NN);
    // bufB = h + segment_sum(h[src] -> dst)
    scatter_add<<<scat_blocks, 256>>>(bufA, ei, bufB);
    // h = relu(bufB@W4+b4)
    gemm_tc<false, false><<<gemm_blocks, 256, SM_TOT>>>(
        bufB, W4, b4, nullptr, nullptr, nullptr, nullptr, bufA, nullptr, NN);
    // out = segment_sum(h, batch)
    zero_out<<<(GG * HD + 255) / 256, 256>>>(out, GG * HD);
    seg_sum<<<seg_blocks, 128>>>(bufA, bat, out);
}

// round 5
// speedup vs baseline: 1.1145x; 1.1145x over previous
#include <cuda_runtime.h>
#include <cstdint>

#define NN 50000
#define HD 128
#define EE 640000
#define GG 128

typedef unsigned int u32;

// Scratch ping-pong buffers (25.6 MB each)
__device__ float g_bufA[NN * HD];
__device__ float g_bufB[NN * HD];
__device__ float g_bufC[NN * HD];

// Exact truncation split: hi = a with low 13 mantissa bits cleared (fits tf32),
// lo = a - hi (exact). 3xTF32 error ~2^-22 per product.
__device__ __forceinline__ void split_tf32(float a, u32& hi, u32& lo) {
    u32 h = __float_as_uint(a) & 0xFFFFE000u;
    hi = h;
    lo = __float_as_uint(a - __uint_as_float(h));
}

// NOTE: not volatile — lets ptxas interleave independent MMAs.
__device__ __forceinline__ void mma_tf32(float* d, const u32* a, const u32* b) {
    asm("mma.sync.aligned.m16n8k8.row.col.f32.tf32.tf32.f32 "
        "{%0,%1,%2,%3}, {%4,%5,%6,%7}, {%8,%9}, {%0,%1,%2,%3};"
        : "+f"(d[0]), "+f"(d[1]), "+f"(d[2]), "+f"(d[3])
        : "r"(a[0]), "r"(a[1]), "r"(a[2]), "r"(a[3]), "r"(b[0]), "r"(b[1]));
}

// ---------------------------------------------------------------------------
// Smem layout (bytes). W transposed [n][k] stride 132 (fragment LDS bank =
// 4g+q: conflict-free). A chunks [m][k32] stride 36, double buffered.
// ---------------------------------------------------------------------------
#define WS 132
#define AS 36
#define SM_BB   0
#define SM_SC   512
#define SM_OF   1024
#define SM_W    1536
#define SM_A0   (SM_W + 128 * WS * 4)        // 69120
#define SM_A1   (SM_A0 + 128 * AS * 4)       // 87552
#define SM_TOT  (SM_A1 + 128 * AS * 4)       // 105984 B

// ---------------------------------------------------------------------------
// Split-TF32 GEMM via mma.sync m16n8k8: out[M,128] = epi(A@W + bias).
// Block 128x128, 512 threads / 16 warps, warp tile 32x32 (2 m x 4 n tiles).
// Raw fp32 staged in smem; hi/lo split in registers. Double-buffered A.
// ---------------------------------------------------------------------------
template <bool DO_BN, bool DUAL>
__global__ void __launch_bounds__(512, 1) gemm_tc(
    const float* __restrict__ A, const float* __restrict__ W,
    const float* __restrict__ bias, const float* __restrict__ gam,
    const float* __restrict__ bet, const float* __restrict__ mmean,
    const float* __restrict__ mvar,
    float* __restrict__ out, float* __restrict__ out2, int M)
{
    extern __shared__ char sm[];
    float* const bb = (float*)(sm + SM_BB);
    float* const sc = (float*)(sm + SM_SC);
    float* const of = (float*)(sm + SM_OF);
    float* const ws = (float*)(sm + SM_W);
    float* const ab[2] = { (float*)(sm + SM_A0), (float*)(sm + SM_A1) };

    const int tid = threadIdx.x, wid = tid >> 5, lane = tid & 31;
    const int g = lane >> 2, q = lane & 3;
    const int wm = wid & 3, wn = wid >> 2;       // 4 row-groups x 4 col-groups
    const int row0 = blockIdx.x * 128;

    if (tid < 128) {
        bb[tid] = bias[tid];
        float s = 1.f, o = 0.f;
        if (DO_BN) {
            s = gam[tid] * rsqrtf(mvar[tid] + 1e-3f);
            o = bet[tid] - mmean[tid] * s;
        }
        sc[tid] = s;
        of[tid] = o;
    }

    // Preload W transposed into [n][k] raw fp32.
#pragma unroll
    for (int i = 0; i < 8; i++) {
        int idx = tid + i * 512;                 // 4096 float4 slots
        int k = idx >> 5;                        // 0..127
        int nq = idx & 31;
        float4 v = *(const float4*)(W + (size_t)k * HD + nq * 4);
        ws[(nq * 4 + 0) * WS + k] = v.x;
        ws[(nq * 4 + 1) * WS + k] = v.y;
        ws[(nq * 4 + 2) * WS + k] = v.z;
        ws[(nq * 4 + 3) * WS + k] = v.w;
    }

    float d[2][4][4];
#pragma unroll
    for (int mt = 0; mt < 2; mt++)
#pragma unroll
        for (int nt = 0; nt < 4; nt++)
#pragma unroll
            for (int c = 0; c < 4; c++) d[mt][nt][c] = 0.f;

    // Chunk loader: 128 rows x 32 k = 1024 float4 / 512 threads = 2 each.
    int lr[2], lk[2];
#pragma unroll
    for (int i = 0; i < 2; i++) {
        int idx = tid + i * 512;
        lr[i] = idx >> 3;
        lk[i] = (idx & 7) * 4;
    }
    float4 pre[2];
#pragma unroll
    for (int i = 0; i < 2; i++) {
        int grow = row0 + lr[i];
        pre[i] = make_float4(0.f, 0.f, 0.f, 0.f);
        if (grow < M)
            pre[i] = *(const float4*)(A + (size_t)grow * HD + lk[i]);
    }
#pragma unroll
    for (int i = 0; i < 2; i++)
        *(float4*)&ab[0][lr[i] * AS + lk[i]] = pre[i];
    __syncthreads();

#pragma unroll 1
    for (int ch = 0; ch < 4; ++ch) {
        // Prefetch next chunk (LDG overlaps compute below).
        if (ch < 3) {
#pragma unroll
            for (int i = 0; i < 2; i++) {
                int grow = row0 + lr[i];
                pre[i] = make_float4(0.f, 0.f, 0.f, 0.f);
                if (grow < M)
                    pre[i] = *(const float4*)(A + (size_t)grow * HD +
                                              (ch + 1) * 32 + lk[i]);
            }
        }

        const float* a = ab[ch & 1];
#pragma unroll
        for (int ks = 0; ks < 4; ++ks) {
            const int kl = ks * 8;
            const int kw = ch * 32 + kl;
            u32 fa_hi[2][4], fa_lo[2][4];
#pragma unroll
            for (int mt = 0; mt < 2; mt++) {
                const float* p = &a[(wm * 32 + mt * 16 + g) * AS + kl + q];
                split_tf32(p[0],          fa_hi[mt][0], fa_lo[mt][0]);
                split_tf32(p[8 * AS],     fa_hi[mt][1], fa_lo[mt][1]);
                split_tf32(p[4],          fa_hi[mt][2], fa_lo[mt][2]);
                split_tf32(p[8 * AS + 4], fa_hi[mt][3], fa_lo[mt][3]);
            }
            u32 fb_hi[4][2], fb_lo[4][2];
#pragma unroll
            for (int nt = 0; nt < 4; nt++) {
                const float* p = &ws[(wn * 32 + nt * 8 + g) * WS + kw + q];
                split_tf32(p[0], fb_hi[nt][0], fb_lo[nt][0]);
                split_tf32(p[4], fb_hi[nt][1], fb_lo[nt][1]);
            }
            // Pass-outermost: 8 independent accumulators between RAW reuses.
#pragma unroll
            for (int mt = 0; mt < 2; mt++)
#pragma unroll
                for (int nt = 0; nt < 4; nt++)
                    mma_tf32(d[mt][nt], fa_hi[mt], fb_hi[nt]);
#pragma unroll
            for (int mt = 0; mt < 2; mt++)
#pragma unroll
                for (int nt = 0; nt < 4; nt++)
                    mma_tf32(d[mt][nt], fa_hi[mt], fb_lo[nt]);
#pragma unroll
            for (int mt = 0; mt < 2; mt++)
#pragma unroll
                for (int nt = 0; nt < 4; nt++)
                    mma_tf32(d[mt][nt], fa_lo[mt], fb_hi[nt]);
        }

        if (ch < 3) {
            float* nb = ab[(ch + 1) & 1];
#pragma unroll
            for (int i = 0; i < 2; i++)
                *(float4*)&nb[lr[i] * AS + lk[i]] = pre[i];
            __syncthreads();
        }
    }

    // Epilogue: c0/c1 at (g, 2q/2q+1), c2/c3 at (g+8, same cols).
    const int q2 = q * 2;
#pragma unroll
    for (int mt = 0; mt < 2; mt++) {
        int r0 = row0 + wm * 32 + mt * 16 + g;
#pragma unroll
        for (int nt = 0; nt < 4; nt++) {
            int col = wn * 32 + nt * 8 + q2;
            float s0 = sc[col], s1 = sc[col + 1];
            float o0 = of[col], o1 = of[col + 1];
            float B0 = bb[col], B1 = bb[col + 1];
            float v0 = fmaxf(d[mt][nt][0] + B0, 0.f) * s0 + o0;
            float v1 = fmaxf(d[mt][nt][1] + B1, 0.f) * s1 + o1;
            float v2 = fmaxf(d[mt][nt][2] + B0, 0.f) * s0 + o0;
            float v3 = fmaxf(d[mt][nt][3] + B1, 0.f) * s1 + o1;
            if (r0 < M) {
                *(float2*)(out + (size_t)r0 * HD + col) = make_float2(v0, v1);
                if (DUAL)
                    *(float2*)(out2 + (size_t)r0 * HD + col) = make_float2(v0, v1);
            }
            if (r0 + 8 < M) {
                *(float2*)(out + (size_t)(r0 + 8) * HD + col) = make_float2(v2, v3);
                if (DUAL)
                    *(float2*)(out2 + (size_t)(r0 + 8) * HD + col) = make_float2(v2, v3);
            }
        }
    }
}

// ---------------------------------------------------------------------------
// Edge scatter-add: out[dst,:] += h[src,:]. One warp per edge; one float4
// gather + one red.global.add.v4.f32 per lane. h is L2-resident.
// ---------------------------------------------------------------------------
__global__ void scatter_add(const float* __restrict__ h,
                            const int* __restrict__ ei,
                            float* __restrict__ out)
{
    int t = blockIdx.x * blockDim.x + threadIdx.x;
    if (t >= EE * 32) return;
    int e = t >> 5;
    int j = t & 31;
    int src = __ldg(ei + 2 * e);
    int dst = __ldg(ei + 2 * e + 1);
    float4 v = __ldg((const float4*)(h + (size_t)src * HD) + j);
    float4* o = (float4*)(out + (size_t)dst * HD) + j;
    asm volatile("red.global.add.v4.f32 [%0], {%1, %2, %3, %4};"
                 :: "l"(o), "f"(v.x), "f"(v.y), "f"(v.z), "f"(v.w)
                 : "memory");
}

// ---------------------------------------------------------------------------
// Final graph readout: out[batch[n],:] += h[n,:], batch sorted -> chunked
// register accumulation, one atomic per group boundary.
// ---------------------------------------------------------------------------
#define SEG_CH 64
__global__ void seg_sum(const float* __restrict__ h,
                        const int* __restrict__ batch,
                        float* __restrict__ out)
{
    int n0 = blockIdx.x * SEG_CH;
    if (n0 >= NN) return;
    int j = threadIdx.x;            // 0..127
    int nend = n0 + SEG_CH;
    if (nend > NN) nend = NN;
    float acc = 0.f;
    int cur = __ldg(batch + n0);
    for (int n = n0; n < nend; ++n) {
        int b = __ldg(batch + n);
        if (b != cur) {
            atomicAdd(out + (size_t)cur * HD + j, acc);
            acc = 0.f;
            cur = b;
        }
        acc += __ldg(h + (size_t)n * HD + j);
    }
    atomicAdd(out + (size_t)cur * HD + j, acc);
}

__global__ void zero_out(float* __restrict__ out, int n)
{
    int t = blockIdx.x * blockDim.x + threadIdx.x;
    if (t < n) out[t] = 0.f;
}

extern "C" void kernel_launch(void* const* d_in, const int* in_sizes, int n_in,
                              void* d_out, int out_size)
{
    const float* x   = (const float*)d_in[0];
    const int*   ei  = (const int*)d_in[1];
    const int*   bat = (const int*)d_in[2];
    const float* W1  = (const float*)d_in[3];
    const float* b1  = (const float*)d_in[4];
    const float* g1  = (const float*)d_in[5];
    const float* be1 = (const float*)d_in[6];
    const float* mm1 = (const float*)d_in[7];
    const float* mv1 = (const float*)d_in[8];
    const float* W2  = (const float*)d_in[9];
    const float* b2  = (const float*)d_in[10];
    const float* W3  = (const float*)d_in[11];
    const float* b3  = (const float*)d_in[12];
    const float* g2  = (const float*)d_in[13];
    const float* be2 = (const float*)d_in[14];
    const float* mm2 = (const float*)d_in[15];
    const float* mv2 = (const float*)d_in[16];
    const float* W4  = (const float*)d_in[17];
    const float* b4  = (const float*)d_in[18];
    float* out = (float*)d_out;

    float *bufA, *bufB, *bufC;
    cudaGetSymbolAddress((void**)&bufA, g_bufA);
    cudaGetSymbolAddress((void**)&bufB, g_bufB);
    cudaGetSymbolAddress((void**)&bufC, g_bufC);

    static bool attr_done = false;
    if (!attr_done) {
        cudaFuncSetAttribute(gemm_tc<true, false>,
                             cudaFuncAttributeMaxDynamicSharedMemorySize, SM_TOT);
        cudaFuncSetAttribute(gemm_tc<false, true>,
                             cudaFuncAttributeMaxDynamicSharedMemorySize, SM_TOT);
        cudaFuncSetAttribute(gemm_tc<true, true>,
                             cudaFuncAttributeMaxDynamicSharedMemorySize, SM_TOT);
        cudaFuncSetAttribute(gemm_tc<false, false>,
                             cudaFuncAttributeMaxDynamicSharedMemorySize, SM_TOT);
        attr_done = true;
    }

    const int gemm_blocks = (NN + 127) / 128;         // 391
    const int scat_blocks = (EE * 32 + 255) / 256;    // 80000
    const int seg_blocks  = (NN + SEG_CH - 1) / SEG_CH;

    // h = bn1(relu(x@W1+b1))
    gemm_tc<true, false><<<gemm_blocks, 512, SM_TOT>>>(
        x, W1, b1, g1, be1, mm1, mv1, bufA, nullptr, NN);
    // h = relu(h@W2+b2); bufB = h, bufC = h (agg accumulator init)
    gemm_tc<false, true><<<gemm_blocks, 512, SM_TOT>>>(
        bufA, W2, b2, nullptr, nullptr, nullptr, nullptr, bufB, bufC, NN);
    // bufC = h + segment_sum(h[src] -> dst)
    scatter_add<<<scat_blocks, 256>>>(bufB, ei, bufC);
    // h = bn2(relu(bufC@W3+b3)); bufA = h, bufB = h (agg accumulator init)
    gemm_tc<true, true><<<gemm_blocks, 512, SM_TOT>>>(
        bufC, W3, b3, g2, be2, mm2, mv2, bufA, bufB, NN);
    // bufB = h + segment_sum(h[src] -> dst)
    scatter_add<<<scat_blocks, 256>>>(bufA, ei, bufB);
    // h = relu(bufB@W4+b4)
    gemm_tc<false, false><<<gemm_blocks, 512, SM_TOT>>>(
        bufB, W4, b4, nullptr, nullptr, nullptr, nullptr, bufA, nullptr, NN);
    // out = segment_sum(h, batch)
    zero_out<<<(GG * HD + 255) / 256, 256>>>(out, GG * HD);
    seg_sum<<<seg_blocks, 128>>>(bufA, bat, out);
}

// round 6
// speedup vs baseline: 1.5985x; 1.4342x over previous
#include <cuda_runtime.h>
#include <cuda_fp16.h>

#define NN 50000
#define HD 128
#define EE 640000
#define GG 128

typedef unsigned int u32;
typedef unsigned short u16;
typedef unsigned long long u64;

// Scratch buffers
__device__ float g_bufA[NN * HD];
__device__ float g_bufB[NN * HD];
__device__ float g_bufC[NN * HD];
// Pre-split W: [layer][hi/lo][16384 halves], already in swizzled smem image.
__device__ __align__(16) u16 g_wsp[4 * 2 * 16384];

__device__ __forceinline__ u32 smem_u32(const void* p) {
    u32 a;
    asm("{ .reg .u64 t; cvta.to.shared.u64 t, %1; cvt.u32.u64 %0, t; }"
        : "=r"(a) : "l"(p));
    return a;
}

__device__ __forceinline__ void mma_f16(float* d, const u32* a, const u32* b) {
    asm("mma.sync.aligned.m16n8k16.row.col.f32.f16.f16.f32 "
        "{%0,%1,%2,%3}, {%4,%5,%6,%7}, {%8,%9}, {%0,%1,%2,%3};"
        : "+f"(d[0]), "+f"(d[1]), "+f"(d[2]), "+f"(d[3])
        : "r"(a[0]), "r"(a[1]), "r"(a[2]), "r"(a[3]), "r"(b[0]), "r"(b[1]));
}
__device__ __forceinline__ void ldsm4(u32* r, u32 addr) {
    asm volatile("ldmatrix.sync.aligned.m8n8.x4.shared.b16 {%0,%1,%2,%3}, [%4];"
                 : "=r"(r[0]), "=r"(r[1]), "=r"(r[2]), "=r"(r[3]) : "r"(addr));
}

// Swizzled half-index inside a [rows][32 halves] tile (64B rows):
// 16B unit j = kh>>3 gets XORed with (r>>1)&3 -> ldmatrix conflict-free.
__device__ __forceinline__ int swz_idx(int r, int kh) {
    return r * 32 + ((((kh >> 3) ^ ((r >> 1) & 3)) << 3) | (kh & 7));
}

// ---------------------------------------------------------------------------
// Prep: split all 4 weight matrices into f16 hi/lo, transposed to [n][k],
// k-chunked (4 chunks of 32), swizzled — the exact smem image GEMM CTAs copy.
// ---------------------------------------------------------------------------
__global__ void prep_w(const float* __restrict__ W1, const float* __restrict__ W2,
                       const float* __restrict__ W3, const float* __restrict__ W4,
                       u16* __restrict__ out)
{
    int t = blockIdx.x * 256 + threadIdx.x;     // 65536 total
    int layer = t >> 14, e = t & 16383;
    int k = e >> 7, n = e & 127;                // W is [k][n] row-major
    const float* W = layer == 0 ? W1 : layer == 1 ? W2 : layer == 2 ? W3 : W4;
    float v = W[k * HD + n];
    __half hi = __float2half_rn(v);
    __half lo = __float2half_rn(v - __half2float(hi));
    int ch = k >> 5, kh = k & 31;
    int idx = ch * 4096 + swz_idx(n, kh);
    int base = layer * 32768;
    out[base + idx]         = __half_as_ushort(hi);
    out[base + 16384 + idx] = __half_as_ushort(lo);
}

// ---------------------------------------------------------------------------
// Smem layout (bytes)
// ---------------------------------------------------------------------------
#define SM_BB  0
#define SM_SC  512
#define SM_OF  1024
#define SM_W   1536                       // W hi (32KB) + W lo (32KB)
#define SM_A   (SM_W + 65536)            // 2 bufs x (hi 4KB + lo 4KB)
#define SM_TOT (SM_A + 16384)            // 83456 B -> 2 CTAs/SM

// ---------------------------------------------------------------------------
// Split-f16 GEMM (3xF16): out[M,128] = epi(A@W + bias), epi = relu [*sc+of].
// CTA 256 thr / 8 warps (2x4), tile 64 rows x 128 cols, warp tile 32x32.
// m16n8k16 HMMA, all fragments via ldmatrix.x4 from swizzled smem.
// ---------------------------------------------------------------------------
template <bool DO_BN, bool DUAL>
__global__ void __launch_bounds__(256, 2) gemm_f16(
    const float* __restrict__ A, const u16* __restrict__ wsp,
    const float* __restrict__ bias, const float* __restrict__ gam,
    const float* __restrict__ bet, const float* __restrict__ mmean,
    const float* __restrict__ mvar,
    float* __restrict__ out, float* __restrict__ out2, int M)
{
    extern __shared__ char sm[];
    const u32 sb = smem_u32(sm);
    float* const bbp = (float*)(sm + SM_BB);
    float* const scp = (float*)(sm + SM_SC);
    float* const ofp = (float*)(sm + SM_OF);

    const int tid = threadIdx.x, wid = tid >> 5, lane = tid & 31;
    const int g = lane >> 2, q = lane & 3;
    const int wm = wid & 1, wn = wid >> 1;       // 2 row x 4 col warp groups
    const int row0 = blockIdx.x * 64;

    if (tid < 128) {
        bbp[tid] = bias[tid];
        float s = 1.f, o = 0.f;
        if (DO_BN) {
            s = gam[tid] * rsqrtf(mvar[tid] + 1e-3f);
            o = bet[tid] - mmean[tid] * s;
        }
        scp[tid] = s;
        ofp[tid] = o;
    }

    // Verbatim copy of pre-swizzled W hi+lo (65536 B = 4096 float4).
    {
        const float4* wg = (const float4*)wsp;
        float4* wsm = (float4*)(sm + SM_W);
#pragma unroll
        for (int i = 0; i < 16; i++)
            wsm[tid + i * 256] = wg[tid + i * 256];
    }

    float d[2][4][4];
#pragma unroll
    for (int mt = 0; mt < 2; mt++)
#pragma unroll
        for (int nt = 0; nt < 4; nt++)
#pragma unroll
            for (int c = 0; c < 4; c++) d[mt][nt][c] = 0.f;

    // A chunk staging: 64 rows x 32 k = 512 float4, 2 per thread.
    const int i0 = tid, i1 = tid + 256;
    const int lr0 = i0 >> 3, lk0 = (i0 & 7) * 4;
    const int lr1 = i1 >> 3, lk1 = (i1 & 7) * 4;

    auto stage = [&](int buf, int r, int k0, float4 v) {
        __half hx = __float2half_rn(v.x), hy = __float2half_rn(v.y),
               hz = __float2half_rn(v.z), hw = __float2half_rn(v.w);
        union { u16 s[4]; u64 u; } hp, lp;
        hp.s[0] = __half_as_ushort(hx); hp.s[1] = __half_as_ushort(hy);
        hp.s[2] = __half_as_ushort(hz); hp.s[3] = __half_as_ushort(hw);
        lp.s[0] = __half_as_ushort(__float2half_rn(v.x - __half2float(hx)));
        lp.s[1] = __half_as_ushort(__float2half_rn(v.y - __half2float(hy)));
        lp.s[2] = __half_as_ushort(__float2half_rn(v.z - __half2float(hz)));
        lp.s[3] = __half_as_ushort(__float2half_rn(v.w - __half2float(hw)));
        int hidx = swz_idx(r, k0);               // half index (8B aligned)
        u64* ph = (u64*)(sm + SM_A + buf * 8192 + hidx * 2);
        u64* pl = (u64*)(sm + SM_A + buf * 8192 + 4096 + hidx * 2);
        *ph = hp.u;
        *pl = lp.u;
    };
    auto fetch = [&](int ch, int r, int k0) -> float4 {
        int grow = row0 + r;
        float4 v = make_float4(0.f, 0.f, 0.f, 0.f);
        if (grow < M)
            v = *(const float4*)(A + (size_t)grow * HD + ch * 32 + k0);
        return v;
    };

    stage(0, lr0, lk0, fetch(0, lr0, lk0));
    stage(0, lr1, lk1, fetch(0, lr1, lk1));
    __syncthreads();

#pragma unroll 1
    for (int ch = 0; ch < 4; ++ch) {
        float4 p0, p1;
        if (ch < 3) {                            // prefetch next chunk
            p0 = fetch(ch + 1, lr0, lk0);
            p1 = fetch(ch + 1, lr1, lk1);
        }

        const u32 abase = sb + SM_A + (ch & 1) * 8192;
        const u32 wbase = sb + SM_W + ch * 8192;
#pragma unroll
        for (int s = 0; s < 2; ++s) {
            // A fragments (hi & lo) via ldmatrix.x4
            u32 fa_hi[2][4], fa_lo[2][4];
            const int ar = wm * 32 + (lane & 7) + ((lane & 8) ? 8 : 0);
            const int aj = s * 2 + ((lane & 16) ? 1 : 0);
#pragma unroll
            for (int mt = 0; mt < 2; mt++) {
                int r = ar + mt * 16;
                u32 off = (u32)(r * 64 + ((aj ^ ((r >> 1) & 3)) << 4));
                ldsm4(fa_hi[mt], abase + off);
                ldsm4(fa_lo[mt], abase + 4096 + off);
            }
            // B fragments
            u32 fb_hi[4][2], fb_lo[4][2];
            const int brb = wn * 32 + ((lane & 16) ? 8 : 0) + (lane & 7);
            const int bj = s * 2 + ((lane & 8) ? 1 : 0);
#pragma unroll
            for (int t = 0; t < 2; t++) {
                int r = brb + t * 16;
                u32 off = (u32)(r * 64 + ((bj ^ ((r >> 1) & 3)) << 4));
                u32 tmp[4];
                ldsm4(tmp, wbase + off);
                fb_hi[2 * t][0] = tmp[0]; fb_hi[2 * t][1] = tmp[1];
                fb_hi[2 * t + 1][0] = tmp[2]; fb_hi[2 * t + 1][1] = tmp[3];
                ldsm4(tmp, wbase + 32768 + off);
                fb_lo[2 * t][0] = tmp[0]; fb_lo[2 * t][1] = tmp[1];
                fb_lo[2 * t + 1][0] = tmp[2]; fb_lo[2 * t + 1][1] = tmp[3];
            }
            // Pass-outermost: 8 independent accumulators between RAW reuses.
#pragma unroll
            for (int mt = 0; mt < 2; mt++)
#pragma unroll
                for (int nt = 0; nt < 4; nt++)
                    mma_f16(d[mt][nt], fa_hi[mt], fb_hi[nt]);
#pragma unroll
            for (int mt = 0; mt < 2; mt++)
#pragma unroll
                for (int nt = 0; nt < 4; nt++)
                    mma_f16(d[mt][nt], fa_hi[mt], fb_lo[nt]);
#pragma unroll
            for (int mt = 0; mt < 2; mt++)
#pragma unroll
                for (int nt = 0; nt < 4; nt++)
                    mma_f16(d[mt][nt], fa_lo[mt], fb_hi[nt]);
        }

        if (ch < 3) {
            __syncthreads();                     // ldmatrix done on this buf
            stage((ch + 1) & 1, lr0, lk0, p0);
            stage((ch + 1) & 1, lr1, lk1, p1);
            __syncthreads();
        }
    }

    // Epilogue: c0/c1 -> (row g, col 2q,2q+1), c2/c3 -> row g+8.
    const int q2 = q * 2;
#pragma unroll
    for (int mt = 0; mt < 2; mt++) {
        int r0 = row0 + wm * 32 + mt * 16 + g;
#pragma unroll
        for (int nt = 0; nt < 4; nt++) {
            int col = wn * 32 + nt * 8 + q2;
            float s0 = scp[col], s1 = scp[col + 1];
            float o0 = ofp[col], o1 = ofp[col + 1];
            float B0 = bbp[col], B1 = bbp[col + 1];
            float v0 = fmaxf(d[mt][nt][0] + B0, 0.f) * s0 + o0;
            float v1 = fmaxf(d[mt][nt][1] + B1, 0.f) * s1 + o1;
            float v2 = fmaxf(d[mt][nt][2] + B0, 0.f) * s0 + o0;
            float v3 = fmaxf(d[mt][nt][3] + B1, 0.f) * s1 + o1;
            if (r0 < M) {
                *(float2*)(out + (size_t)r0 * HD + col) = make_float2(v0, v1);
                if (DUAL)
                    *(float2*)(out2 + (size_t)r0 * HD + col) = make_float2(v0, v1);
            }
            if (r0 + 8 < M) {
                *(float2*)(out + (size_t)(r0 + 8) * HD + col) = make_float2(v2, v3);
                if (DUAL)
                    *(float2*)(out2 + (size_t)(r0 + 8) * HD + col) = make_float2(v2, v3);
            }
        }
    }
}

// ---------------------------------------------------------------------------
// Edge scatter-add: out[dst,:] += h[src,:]. One warp per edge; one float4
// gather + one red.global.add.v4.f32 per lane. h is L2-resident.
// ---------------------------------------------------------------------------
__global__ void scatter_add(const float* __restrict__ h,
                            const int* __restrict__ ei,
                            float* __restrict__ out)
{
    int t = blockIdx.x * blockDim.x + threadIdx.x;
    if (t >= EE * 32) return;
    int e = t >> 5;
    int j = t & 31;
    int src = __ldg(ei + 2 * e);
    int dst = __ldg(ei + 2 * e + 1);
    float4 v = __ldg((const float4*)(h + (size_t)src * HD) + j);
    float4* o = (float4*)(out + (size_t)dst * HD) + j;
    asm volatile("red.global.add.v4.f32 [%0], {%1, %2, %3, %4};"
                 :: "l"(o), "f"(v.x), "f"(v.y), "f"(v.z), "f"(v.w)
                 : "memory");
}

// ---------------------------------------------------------------------------
// Final graph readout: sorted batch -> chunked register accumulation.
// ---------------------------------------------------------------------------
#define SEG_CH 64
__global__ void seg_sum(const float* __restrict__ h,
                        const int* __restrict__ batch,
                        float* __restrict__ out)
{
    int n0 = blockIdx.x * SEG_CH;
    if (n0 >= NN) return;
    int j = threadIdx.x;            // 0..127
    int nend = n0 + SEG_CH;
    if (nend > NN) nend = NN;
    float acc = 0.f;
    int cur = __ldg(batch + n0);
    for (int n = n0; n < nend; ++n) {
        int b = __ldg(batch + n);
        if (b != cur) {
            atomicAdd(out + (size_t)cur * HD + j, acc);
            acc = 0.f;
            cur = b;
        }
        acc += __ldg(h + (size_t)n * HD + j);
    }
    atomicAdd(out + (size_t)cur * HD + j, acc);
}

__global__ void zero_out(float* __restrict__ out, int n)
{
    int t = blockIdx.x * blockDim.x + threadIdx.x;
    if (t < n) out[t] = 0.f;
}

extern "C" void kernel_launch(void* const* d_in, const int* in_sizes, int n_in,
                              void* d_out, int out_size)
{
    const float* x   = (const float*)d_in[0];
    const int*   ei  = (const int*)d_in[1];
    const int*   bat = (const int*)d_in[2];
    const float* W1  = (const float*)d_in[3];
    const float* b1  = (const float*)d_in[4];
    const float* g1  = (const float*)d_in[5];
    const float* be1 = (const float*)d_in[6];
    const float* mm1 = (const float*)d_in[7];
    const float* mv1 = (const float*)d_in[8];
    const float* W2  = (const float*)d_in[9];
    const float* b2  = (const float*)d_in[10];
    const float* W3  = (const float*)d_in[11];
    const float* b3  = (const float*)d_in[12];
    const float* g2  = (const float*)d_in[13];
    const float* be2 = (const float*)d_in[14];
    const float* mm2 = (const float*)d_in[15];
    const float* mv2 = (const float*)d_in[16];
    const float* W4  = (const float*)d_in[17];
    const float* b4  = (const float*)d_in[18];
    float* out = (float*)d_out;

    float *bufA, *bufB, *bufC;
    u16* wsp;
    cudaGetSymbolAddress((void**)&bufA, g_bufA);
    cudaGetSymbolAddress((void**)&bufB, g_bufB);
    cudaGetSymbolAddress((void**)&bufC, g_bufC);
    cudaGetSymbolAddress((void**)&wsp, g_wsp);

    cudaFuncSetAttribute(gemm_f16<true, false>,
                         cudaFuncAttributeMaxDynamicSharedMemorySize, SM_TOT);
    cudaFuncSetAttribute(gemm_f16<false, true>,
                         cudaFuncAttributeMaxDynamicSharedMemorySize, SM_TOT);
    cudaFuncSetAttribute(gemm_f16<true, true>,
                         cudaFuncAttributeMaxDynamicSharedMemorySize, SM_TOT);
    cudaFuncSetAttribute(gemm_f16<false, false>,
                         cudaFuncAttributeMaxDynamicSharedMemorySize, SM_TOT);

    const int gemm_blocks = (NN + 63) / 64;           // 782
    const int scat_blocks = (EE * 32 + 255) / 256;    // 80000
    const int seg_blocks  = (NN + SEG_CH - 1) / SEG_CH;

    // Split all W into f16 hi/lo swizzled images.
    prep_w<<<256, 256>>>(W1, W2, W3, W4, wsp);

    // h = bn1(relu(x@W1+b1))
    gemm_f16<true, false><<<gemm_blocks, 256, SM_TOT>>>(
        x, wsp + 0 * 32768, b1, g1, be1, mm1, mv1, bufA, nullptr, NN);
    // h = relu(h@W2+b2); bufB = h, bufC = h (agg accumulator init)
    gemm_f16<false, true><<<gemm_blocks, 256, SM_TOT>>>(
        bufA, wsp + 1 * 32768, b2, nullptr, nullptr, nullptr, nullptr,
        bufB, bufC, NN);
    // bufC = h + segment_sum(h[src] -> dst)
    scatter_add<<<scat_blocks, 256>>>(bufB, ei, bufC);
    // h = bn2(relu(bufC@W3+b3)); bufA = h, bufB = h (agg accumulator init)
    gemm_f16<true, true><<<gemm_blocks, 256, SM_TOT>>>(
        bufC, wsp + 2 * 32768, b3, g2, be2, mm2, mv2, bufA, bufB, NN);
    // bufB = h + segment_sum(h[src] -> dst)
    scatter_add<<<scat_blocks, 256>>>(bufA, ei, bufB);
    // h = relu(bufB@W4+b4)
    gemm_f16<false, false><<<gemm_blocks, 256, SM_TOT>>>(
        bufB, wsp + 3 * 32768, b4, nullptr, nullptr, nullptr, nullptr,
        bufA, nullptr, NN);
    // out = segment_sum(h, batch)
    zero_out<<<(GG * HD + 255) / 256, 256>>>(out, GG * HD);
    seg_sum<<<seg_blocks, 128>>>(bufA, bat, out);
}

// round 7
// speedup vs baseline: 2.1706x; 1.3579x over previous
#include <cuda_runtime.h>
#include <cuda_fp16.h>

#define NN 50000
#define HD 128
#define EE 640000
#define GG 128

typedef unsigned int u32;
typedef unsigned short u16;
typedef unsigned long long u64;

// Scratch buffers
__device__ float g_bufA[NN * HD];
__device__ float g_bufB[NN * HD];
__device__ float g_bufC[NN * HD];
// Pre-split W: [layer][hi/lo][16384 halves], swizzled smem image.
__device__ __align__(16) u16 g_wsp[4 * 2 * 16384];
// CSR-by-dst scratch
__device__ int g_rp[NN + 1];      // row pointers
__device__ int g_cur[NN];         // counts, then placement cursors
__device__ int g_ssrc[EE];        // src ids sorted by dst
__device__ int g_bsum[256];       // per-block partial sums for scan

#define SCAN_B 196                // ceil(50000/256)

__device__ __forceinline__ u32 smem_u32(const void* p) {
    u32 a;
    asm("{ .reg .u64 t; cvta.to.shared.u64 t, %1; cvt.u32.u64 %0, t; }"
        : "=r"(a) : "l"(p));
    return a;
}
__device__ __forceinline__ void mma_f16(float* d, const u32* a, const u32* b) {
    asm("mma.sync.aligned.m16n8k16.row.col.f32.f16.f16.f32 "
        "{%0,%1,%2,%3}, {%4,%5,%6,%7}, {%8,%9}, {%0,%1,%2,%3};"
        : "+f"(d[0]), "+f"(d[1]), "+f"(d[2]), "+f"(d[3])
        : "r"(a[0]), "r"(a[1]), "r"(a[2]), "r"(a[3]), "r"(b[0]), "r"(b[1]));
}
__device__ __forceinline__ void ldsm4(u32* r, u32 addr) {
    asm volatile("ldmatrix.sync.aligned.m8n8.x4.shared.b16 {%0,%1,%2,%3}, [%4];"
                 : "=r"(r[0]), "=r"(r[1]), "=r"(r[2]), "=r"(r[3]) : "r"(addr));
}
__device__ __forceinline__ int swz_idx(int r, int kh) {
    return r * 32 + ((((kh >> 3) ^ ((r >> 1) & 3)) << 3) | (kh & 7));
}

// ---------------------------------------------------------------------------
// W prep: f16 hi/lo split, transposed [n][k], k-chunked, swizzled.
// ---------------------------------------------------------------------------
__global__ void prep_w(const float* __restrict__ W1, const float* __restrict__ W2,
                       const float* __restrict__ W3, const float* __restrict__ W4,
                       u16* __restrict__ out)
{
    int t = blockIdx.x * 256 + threadIdx.x;
    int layer = t >> 14, e = t & 16383;
    int k = e >> 7, n = e & 127;
    const float* W = layer == 0 ? W1 : layer == 1 ? W2 : layer == 2 ? W3 : W4;
    float v = W[k * HD + n];
    __half hi = __float2half_rn(v);
    __half lo = __float2half_rn(v - __half2float(hi));
    int ch = k >> 5, kh = k & 31;
    int idx = ch * 4096 + swz_idx(n, kh);
    int base = layer * 32768;
    out[base + idx]         = __half_as_ushort(hi);
    out[base + 16384 + idx] = __half_as_ushort(lo);
}

// ---------------------------------------------------------------------------
// CSR build: zero counts -> histogram(dst) -> 3-step scan -> edge placement.
// ---------------------------------------------------------------------------
__global__ void csr_zero(int* __restrict__ cnt)
{
    int t = blockIdx.x * blockDim.x + threadIdx.x;
    if (t < NN) cnt[t] = 0;
}
__global__ void csr_hist(const int* __restrict__ ei, int* __restrict__ cnt)
{
    int e = blockIdx.x * blockDim.x + threadIdx.x;
    if (e < EE) atomicAdd(cnt + __ldg(ei + 2 * e + 1), 1);
}
__global__ void csr_scan1(const int* __restrict__ cnt, int* __restrict__ bsum)
{
    __shared__ int s[256];
    int t = threadIdx.x, i = blockIdx.x * 256 + t;
    s[t] = (i < NN) ? cnt[i] : 0;
    __syncthreads();
    for (int o = 128; o > 0; o >>= 1) {
        if (t < o) s[t] += s[t + o];
        __syncthreads();
    }
    if (t == 0) bsum[blockIdx.x] = s[0];
}
__global__ void csr_scan2(int* __restrict__ bsum, int* __restrict__ rp)
{
    if (threadIdx.x == 0) {
        int run = 0;
        for (int b = 0; b < SCAN_B; b++) {
            int v = bsum[b];
            bsum[b] = run;
            run += v;
        }
        rp[NN] = run;       // == EE
    }
}
__global__ void csr_scan3(const int* __restrict__ cnt, const int* __restrict__ bsum,
                          int* __restrict__ rp, int* __restrict__ cur)
{
    __shared__ int s[256];
    int t = threadIdx.x, i = blockIdx.x * 256 + t;
    int c = (i < NN) ? cnt[i] : 0;
    s[t] = c;
    __syncthreads();
    // Hillis-Steele inclusive scan
    for (int o = 1; o < 256; o <<= 1) {
        int v = (t >= o) ? s[t - o] : 0;
        __syncthreads();
        s[t] += v;
        __syncthreads();
    }
    if (i < NN) {
        int excl = bsum[blockIdx.x] + s[t] - c;
        rp[i] = excl;
        cur[i] = excl;
    }
}
__global__ void csr_place(const int* __restrict__ ei, int* __restrict__ cur,
                          int* __restrict__ ssrc)
{
    int e = blockIdx.x * blockDim.x + threadIdx.x;
    if (e >= EE) return;
    int src = __ldg(ei + 2 * e);
    int dst = __ldg(ei + 2 * e + 1);
    int pos = atomicAdd(cur + dst, 1);
    ssrc[pos] = src;
}

// ---------------------------------------------------------------------------
// Atomic-free aggregate: out[d,:] = h[d,:] + sum_{e in row d} h[ssrc[e],:]
// One warp per dst; lane j holds float4 column j.
// ---------------------------------------------------------------------------
__global__ void __launch_bounds__(256) csr_agg(
    const float* __restrict__ h, const int* __restrict__ rp,
    const int* __restrict__ ssrc, float* __restrict__ out)
{
    int d = (blockIdx.x * blockDim.x + threadIdx.x) >> 5;
    if (d >= NN) return;
    int lane = threadIdx.x & 31;
    float4 acc = __ldg((const float4*)(h + (size_t)d * HD) + lane);
    int e = __ldg(rp + d), e1 = __ldg(rp + d + 1);
    if (e < e1) {
        int s = __ldg(ssrc + e);
        for (++e; e < e1; ++e) {
            int snext = __ldg(ssrc + e);        // prefetch next index
            float4 v = __ldg((const float4*)(h + (size_t)s * HD) + lane);
            acc.x += v.x; acc.y += v.y; acc.z += v.z; acc.w += v.w;
            s = snext;
        }
        float4 v = __ldg((const float4*)(h + (size_t)s * HD) + lane);
        acc.x += v.x; acc.y += v.y; acc.z += v.z; acc.w += v.w;
    }
    *((float4*)(out + (size_t)d * HD) + lane) = acc;
}

// ---------------------------------------------------------------------------
// Smem layout (bytes)
// ---------------------------------------------------------------------------
#define SM_BB  0
#define SM_SC  512
#define SM_OF  1024
#define SM_W   1536
#define SM_A   (SM_W + 65536)
#define SM_TOT (SM_A + 16384)            // 83456 B -> 2 CTAs/SM

// ---------------------------------------------------------------------------
// Split-f16 GEMM (3xF16): out[M,128] = epi(A@W + bias), epi = relu [*sc+of].
// ---------------------------------------------------------------------------
template <bool DO_BN>
__global__ void __launch_bounds__(256, 2) gemm_f16(
    const float* __restrict__ A, const u16* __restrict__ wsp,
    const float* __restrict__ bias, const float* __restrict__ gam,
    const float* __restrict__ bet, const float* __restrict__ mmean,
    const float* __restrict__ mvar, float* __restrict__ out, int M)
{
    extern __shared__ char sm[];
    const u32 sb = smem_u32(sm);
    float* const bbp = (float*)(sm + SM_BB);
    float* const scp = (float*)(sm + SM_SC);
    float* const ofp = (float*)(sm + SM_OF);

    const int tid = threadIdx.x, wid = tid >> 5, lane = tid & 31;
    const int g = lane >> 2, q = lane & 3;
    const int wm = wid & 1, wn = wid >> 1;
    const int row0 = blockIdx.x * 64;

    if (tid < 128) {
        bbp[tid] = bias[tid];
        float s = 1.f, o = 0.f;
        if (DO_BN) {
            s = gam[tid] * rsqrtf(mvar[tid] + 1e-3f);
            o = bet[tid] - mmean[tid] * s;
        }
        scp[tid] = s;
        ofp[tid] = o;
    }
    {
        const float4* wg = (const float4*)wsp;
        float4* wsm = (float4*)(sm + SM_W);
#pragma unroll
        for (int i = 0; i < 16; i++)
            wsm[tid + i * 256] = wg[tid + i * 256];
    }

    float d[2][4][4];
#pragma unroll
    for (int mt = 0; mt < 2; mt++)
#pragma unroll
        for (int nt = 0; nt < 4; nt++)
#pragma unroll
            for (int c = 0; c < 4; c++) d[mt][nt][c] = 0.f;

    const int i0 = tid, i1 = tid + 256;
    const int lr0 = i0 >> 3, lk0 = (i0 & 7) * 4;
    const int lr1 = i1 >> 3, lk1 = (i1 & 7) * 4;

    auto stage = [&](int buf, int r, int k0, float4 v) {
        __half hx = __float2half_rn(v.x), hy = __float2half_rn(v.y),
               hz = __float2half_rn(v.z), hw = __float2half_rn(v.w);
        union { u16 s[4]; u64 u; } hp, lp;
        hp.s[0] = __half_as_ushort(hx); hp.s[1] = __half_as_ushort(hy);
        hp.s[2] = __half_as_ushort(hz); hp.s[3] = __half_as_ushort(hw);
        lp.s[0] = __half_as_ushort(__float2half_rn(v.x - __half2float(hx)));
        lp.s[1] = __half_as_ushort(__float2half_rn(v.y - __half2float(hy)));
        lp.s[2] = __half_as_ushort(__float2half_rn(v.z - __half2float(hz)));
        lp.s[3] = __half_as_ushort(__float2half_rn(v.w - __half2float(hw)));
        int hidx = swz_idx(r, k0);
        *(u64*)(sm + SM_A + buf * 8192 + hidx * 2) = hp.u;
        *(u64*)(sm + SM_A + buf * 8192 + 4096 + hidx * 2) = lp.u;
    };
    auto fetch = [&](int ch, int r, int k0) -> float4 {
        int grow = row0 + r;
        float4 v = make_float4(0.f, 0.f, 0.f, 0.f);
        if (grow < M)
            v = *(const float4*)(A + (size_t)grow * HD + ch * 32 + k0);
        return v;
    };

    stage(0, lr0, lk0, fetch(0, lr0, lk0));
    stage(0, lr1, lk1, fetch(0, lr1, lk1));
    __syncthreads();

#pragma unroll 1
    for (int ch = 0; ch < 4; ++ch) {
        float4 p0, p1;
        if (ch < 3) {
            p0 = fetch(ch + 1, lr0, lk0);
            p1 = fetch(ch + 1, lr1, lk1);
        }
        const u32 abase = sb + SM_A + (ch & 1) * 8192;
        const u32 wbase = sb + SM_W + ch * 8192;
#pragma unroll
        for (int s = 0; s < 2; ++s) {
            u32 fa_hi[2][4], fa_lo[2][4];
            const int ar = wm * 32 + (lane & 7) + ((lane & 8) ? 8 : 0);
            const int aj = s * 2 + ((lane & 16) ? 1 : 0);
#pragma unroll
            for (int mt = 0; mt < 2; mt++) {
                int r = ar + mt * 16;
                u32 off = (u32)(r * 64 + ((aj ^ ((r >> 1) & 3)) << 4));
                ldsm4(fa_hi[mt], abase + off);
                ldsm4(fa_lo[mt], abase + 4096 + off);
            }
            u32 fb_hi[4][2], fb_lo[4][2];
            const int brb = wn * 32 + ((lane & 16) ? 8 : 0) + (lane & 7);
            const int bj = s * 2 + ((lane & 8) ? 1 : 0);
#pragma unroll
            for (int t = 0; t < 2; t++) {
                int r = brb + t * 16;
                u32 off = (u32)(r * 64 + ((bj ^ ((r >> 1) & 3)) << 4));
                u32 tmp[4];
                ldsm4(tmp, wbase + off);
                fb_hi[2 * t][0] = tmp[0]; fb_hi[2 * t][1] = tmp[1];
                fb_hi[2 * t + 1][0] = tmp[2]; fb_hi[2 * t + 1][1] = tmp[3];
                ldsm4(tmp, wbase + 32768 + off);
                fb_lo[2 * t][0] = tmp[0]; fb_lo[2 * t][1] = tmp[1];
                fb_lo[2 * t + 1][0] = tmp[2]; fb_lo[2 * t + 1][1] = tmp[3];
            }
#pragma unroll
            for (int mt = 0; mt < 2; mt++)
#pragma unroll
                for (int nt = 0; nt < 4; nt++)
                    mma_f16(d[mt][nt], fa_hi[mt], fb_hi[nt]);
#pragma unroll
            for (int mt = 0; mt < 2; mt++)
#pragma unroll
                for (int nt = 0; nt < 4; nt++)
                    mma_f16(d[mt][nt], fa_hi[mt], fb_lo[nt]);
#pragma unroll
            for (int mt = 0; mt < 2; mt++)
#pragma unroll
                for (int nt = 0; nt < 4; nt++)
                    mma_f16(d[mt][nt], fa_lo[mt], fb_hi[nt]);
        }
        if (ch < 3) {
            __syncthreads();
            stage((ch + 1) & 1, lr0, lk0, p0);
            stage((ch + 1) & 1, lr1, lk1, p1);
            __syncthreads();
        }
    }

    const int q2 = q * 2;
#pragma unroll
    for (int mt = 0; mt < 2; mt++) {
        int r0 = row0 + wm * 32 + mt * 16 + g;
#pragma unroll
        for (int nt = 0; nt < 4; nt++) {
            int col = wn * 32 + nt * 8 + q2;
            float s0 = scp[col], s1 = scp[col + 1];
            float o0 = ofp[col], o1 = ofp[col + 1];
            float B0 = bbp[col], B1 = bbp[col + 1];
            float v0 = fmaxf(d[mt][nt][0] + B0, 0.f) * s0 + o0;
            float v1 = fmaxf(d[mt][nt][1] + B1, 0.f) * s1 + o1;
            float v2 = fmaxf(d[mt][nt][2] + B0, 0.f) * s0 + o0;
            float v3 = fmaxf(d[mt][nt][3] + B1, 0.f) * s1 + o1;
            if (r0 < M)
                *(float2*)(out + (size_t)r0 * HD + col) = make_float2(v0, v1);
            if (r0 + 8 < M)
                *(float2*)(out + (size_t)(r0 + 8) * HD + col) = make_float2(v2, v3);
        }
    }
}

// ---------------------------------------------------------------------------
// Final graph readout: sorted batch -> chunked register accumulation.
// ---------------------------------------------------------------------------
#define SEG_CH 64
__global__ void seg_sum(const float* __restrict__ h,
                        const int* __restrict__ batch,
                        float* __restrict__ out)
{
    int n0 = blockIdx.x * SEG_CH;
    if (n0 >= NN) return;
    int j = threadIdx.x;
    int nend = n0 + SEG_CH;
    if (nend > NN) nend = NN;
    float acc = 0.f;
    int cur = __ldg(batch + n0);
    for (int n = n0; n < nend; ++n) {
        int b = __ldg(batch + n);
        if (b != cur) {
            atomicAdd(out + (size_t)cur * HD + j, acc);
            acc = 0.f;
            cur = b;
        }
        acc += __ldg(h + (size_t)n * HD + j);
    }
    atomicAdd(out + (size_t)cur * HD + j, acc);
}

__global__ void zero_out(float* __restrict__ out, int n)
{
    int t = blockIdx.x * blockDim.x + threadIdx.x;
    if (t < n) out[t] = 0.f;
}

extern "C" void kernel_launch(void* const* d_in, const int* in_sizes, int n_in,
                              void* d_out, int out_size)
{
    const float* x   = (const float*)d_in[0];
    const int*   ei  = (const int*)d_in[1];
    const int*   bat = (const int*)d_in[2];
    const float* W1  = (const float*)d_in[3];
    const float* b1  = (const float*)d_in[4];
    const float* g1  = (const float*)d_in[5];
    const float* be1 = (const float*)d_in[6];
    const float* mm1 = (const float*)d_in[7];
    const float* mv1 = (const float*)d_in[8];
    const float* W2  = (const float*)d_in[9];
    const float* b2  = (const float*)d_in[10];
    const float* W3  = (const float*)d_in[11];
    const float* b3  = (const float*)d_in[12];
    const float* g2  = (const float*)d_in[13];
    const float* be2 = (const float*)d_in[14];
    const float* mm2 = (const float*)d_in[15];
    const float* mv2 = (const float*)d_in[16];
    const float* W4  = (const float*)d_in[17];
    const float* b4  = (const float*)d_in[18];
    float* out = (float*)d_out;

    float *bufA, *bufB, *bufC;
    u16* wsp;
    int *rp, *cur, *ssrc, *bsum;
    cudaGetSymbolAddress((void**)&bufA, g_bufA);
    cudaGetSymbolAddress((void**)&bufB, g_bufB);
    cudaGetSymbolAddress((void**)&bufC, g_bufC);
    cudaGetSymbolAddress((void**)&wsp, g_wsp);
    cudaGetSymbolAddress((void**)&rp, g_rp);
    cudaGetSymbolAddress((void**)&cur, g_cur);
    cudaGetSymbolAddress((void**)&ssrc, g_ssrc);
    cudaGetSymbolAddress((void**)&bsum, g_bsum);

    cudaFuncSetAttribute(gemm_f16<true>,
                         cudaFuncAttributeMaxDynamicSharedMemorySize, SM_TOT);
    cudaFuncSetAttribute(gemm_f16<false>,
                         cudaFuncAttributeMaxDynamicSharedMemorySize, SM_TOT);

    const int gemm_blocks = (NN + 63) / 64;            // 782
    const int edge_blocks = (EE + 255) / 256;          // 2500
    const int agg_blocks  = (NN * 32 + 255) / 256;     // 6250
    const int seg_blocks  = (NN + SEG_CH - 1) / SEG_CH;

    // W prep + CSR build (overlaps nothing; ~15us total)
    prep_w<<<256, 256>>>(W1, W2, W3, W4, wsp);
    csr_zero<<<(NN + 255) / 256, 256>>>(cur);
    csr_hist<<<edge_blocks, 256>>>(ei, cur);
    csr_scan1<<<SCAN_B, 256>>>(cur, bsum);
    csr_scan2<<<1, 32>>>(bsum, rp);
    csr_scan3<<<SCAN_B, 256>>>(cur, bsum, rp, cur);
    csr_place<<<edge_blocks, 256>>>(ei, cur, ssrc);

    // h = bn1(relu(x@W1+b1))
    gemm_f16<true><<<gemm_blocks, 256, SM_TOT>>>(
        x, wsp + 0 * 32768, b1, g1, be1, mm1, mv1, bufA, NN);
    // h = relu(h@W2+b2)
    gemm_f16<false><<<gemm_blocks, 256, SM_TOT>>>(
        bufA, wsp + 1 * 32768, b2, nullptr, nullptr, nullptr, nullptr, bufB, NN);
    // bufC = bufB + aggregate(bufB)
    csr_agg<<<agg_blocks, 256>>>(bufB, rp, ssrc, bufC);
    // h = bn2(relu(bufC@W3+b3))
    gemm_f16<true><<<gemm_blocks, 256, SM_TOT>>>(
        bufC, wsp + 2 * 32768, b3, g2, be2, mm2, mv2, bufA, NN);
    // bufB = bufA + aggregate(bufA)
    csr_agg<<<agg_blocks, 256>>>(bufA, rp, ssrc, bufB);
    // h = relu(bufB@W4+b4)
    gemm_f16<false><<<gemm_blocks, 256, SM_TOT>>>(
        bufB, wsp + 3 * 32768, b4, nullptr, nullptr, nullptr, nullptr, bufA, NN);
    // out = segment_sum(h, batch)
    zero_out<<<(GG * HD + 255) / 256, 256>>>(out, GG * HD);
    seg_sum<<<seg_blocks, 128>>>(bufA, bat, out);
}

// round 8
// speedup vs baseline: 2.2010x; 1.0140x over previous
#include <cuda_runtime.h>
#include <cuda_fp16.h>

#define NN 50000
#define HD 128
#define EE 640000
#define GG 128

typedef unsigned int u32;
typedef unsigned short u16;
typedef unsigned long long u64;

// Scratch buffers
__device__ float g_bufA[NN * HD];
__device__ float g_bufB[NN * HD];
__device__ float g_bufC[NN * HD];
// Pre-split W: [layer][hi/lo][16384 halves], swizzled smem image.
__device__ __align__(16) u16 g_wsp[4 * 2 * 16384];
// CSR-by-dst scratch
__device__ int g_rp[NN + 1];
__device__ int g_cur[NN];
__device__ int g_ssrc[EE];
__device__ int g_bsum[256];

#define SCAN_B 196

__device__ __forceinline__ u32 smem_u32(const void* p) {
    u32 a;
    asm("{ .reg .u64 t; cvta.to.shared.u64 t, %1; cvt.u32.u64 %0, t; }"
        : "=r"(a) : "l"(p));
    return a;
}
__device__ __forceinline__ void mma_f16(float* d, const u32* a, const u32* b) {
    asm("mma.sync.aligned.m16n8k16.row.col.f32.f16.f16.f32 "
        "{%0,%1,%2,%3}, {%4,%5,%6,%7}, {%8,%9}, {%0,%1,%2,%3};"
        : "+f"(d[0]), "+f"(d[1]), "+f"(d[2]), "+f"(d[3])
        : "r"(a[0]), "r"(a[1]), "r"(a[2]), "r"(a[3]), "r"(b[0]), "r"(b[1]));
}
__device__ __forceinline__ void ldsm4(u32* r, u32 addr) {
    asm volatile("ldmatrix.sync.aligned.m8n8.x4.shared.b16 {%0,%1,%2,%3}, [%4];"
                 : "=r"(r[0]), "=r"(r[1]), "=r"(r[2]), "=r"(r[3]) : "r"(addr));
}
__device__ __forceinline__ void cp16(u32 smem, const void* g) {
    asm volatile("cp.async.cg.shared.global [%0], [%1], 16;"
                 :: "r"(smem), "l"(g) : "memory");
}
__device__ __forceinline__ int swz_idx(int r, int kh) {
    return r * 32 + ((((kh >> 3) ^ ((r >> 1) & 3)) << 3) | (kh & 7));
}

// ---------------------------------------------------------------------------
// W prep: f16 hi/lo split, transposed [n][k], k-chunked, swizzled.
// ---------------------------------------------------------------------------
__global__ void prep_w(const float* __restrict__ W1, const float* __restrict__ W2,
                       const float* __restrict__ W3, const float* __restrict__ W4,
                       u16* __restrict__ out)
{
    int t = blockIdx.x * 256 + threadIdx.x;
    int layer = t >> 14, e = t & 16383;
    int k = e >> 7, n = e & 127;
    const float* W = layer == 0 ? W1 : layer == 1 ? W2 : layer == 2 ? W3 : W4;
    float v = W[k * HD + n];
    __half hi = __float2half_rn(v);
    __half lo = __float2half_rn(v - __half2float(hi));
    int ch = k >> 5, kh = k & 31;
    int idx = ch * 4096 + swz_idx(n, kh);
    int base = layer * 32768;
    out[base + idx]         = __half_as_ushort(hi);
    out[base + 16384 + idx] = __half_as_ushort(lo);
}

// ---------------------------------------------------------------------------
// CSR build
// ---------------------------------------------------------------------------
__global__ void csr_zero(int* __restrict__ cnt)
{
    int t = blockIdx.x * blockDim.x + threadIdx.x;
    if (t < NN) cnt[t] = 0;
}
__global__ void csr_hist(const int* __restrict__ ei, int* __restrict__ cnt)
{
    int e = blockIdx.x * blockDim.x + threadIdx.x;
    if (e < EE) atomicAdd(cnt + __ldg(ei + 2 * e + 1), 1);
}
__global__ void csr_scan1(const int* __restrict__ cnt, int* __restrict__ bsum)
{
    __shared__ int s[256];
    int t = threadIdx.x, i = blockIdx.x * 256 + t;
    s[t] = (i < NN) ? cnt[i] : 0;
    __syncthreads();
    for (int o = 128; o > 0; o >>= 1) {
        if (t < o) s[t] += s[t + o];
        __syncthreads();
    }
    if (t == 0) bsum[blockIdx.x] = s[0];
}
__global__ void csr_scan2(int* __restrict__ bsum, int* __restrict__ rp)
{
    if (threadIdx.x == 0) {
        int run = 0;
        for (int b = 0; b < SCAN_B; b++) {
            int v = bsum[b];
            bsum[b] = run;
            run += v;
        }
        rp[NN] = run;
    }
}
__global__ void csr_scan3(const int* __restrict__ cnt, const int* __restrict__ bsum,
                          int* __restrict__ rp, int* __restrict__ cur)
{
    __shared__ int s[256];
    int t = threadIdx.x, i = blockIdx.x * 256 + t;
    int c = (i < NN) ? cnt[i] : 0;
    s[t] = c;
    __syncthreads();
    for (int o = 1; o < 256; o <<= 1) {
        int v = (t >= o) ? s[t - o] : 0;
        __syncthreads();
        s[t] += v;
        __syncthreads();
    }
    if (i < NN) {
        int excl = bsum[blockIdx.x] + s[t] - c;
        rp[i] = excl;
        cur[i] = excl;
    }
}
__global__ void csr_place(const int* __restrict__ ei, int* __restrict__ cur,
                          int* __restrict__ ssrc)
{
    int e = blockIdx.x * blockDim.x + threadIdx.x;
    if (e >= EE) return;
    int src = __ldg(ei + 2 * e);
    int dst = __ldg(ei + 2 * e + 1);
    int pos = atomicAdd(cur + dst, 1);
    ssrc[pos] = src;
}

// ---------------------------------------------------------------------------
// Atomic-free aggregate: out[d,:] = h[d,:] + sum_{e in row d} h[ssrc[e],:]
// ---------------------------------------------------------------------------
__global__ void __launch_bounds__(256) csr_agg(
    const float* __restrict__ h, const int* __restrict__ rp,
    const int* __restrict__ ssrc, float* __restrict__ out)
{
    int d = (blockIdx.x * blockDim.x + threadIdx.x) >> 5;
    if (d >= NN) return;
    int lane = threadIdx.x & 31;
    float4 acc = __ldg((const float4*)(h + (size_t)d * HD) + lane);
    int e = __ldg(rp + d), e1 = __ldg(rp + d + 1);
    if (e < e1) {
        int s = __ldg(ssrc + e);
        for (++e; e < e1; ++e) {
            int snext = __ldg(ssrc + e);
            float4 v = __ldg((const float4*)(h + (size_t)s * HD) + lane);
            acc.x += v.x; acc.y += v.y; acc.z += v.z; acc.w += v.w;
            s = snext;
        }
        float4 v = __ldg((const float4*)(h + (size_t)s * HD) + lane);
        acc.x += v.x; acc.y += v.y; acc.z += v.z; acc.w += v.w;
    }
    *((float4*)(out + (size_t)d * HD) + lane) = acc;
}

// ---------------------------------------------------------------------------
// Smem layout (bytes). Full-K resident: W (hi 32K + lo 32K), A (4 chunks x
// (hi 8K + lo 8K)).
// ---------------------------------------------------------------------------
#define SM_BB  0
#define SM_SC  512
#define SM_OF  1024
#define SM_W   1536
#define SM_A   (SM_W + 65536)            // 67072
#define SM_TOT (SM_A + 65536)            // 132608 B -> 1 CTA/SM, 16 warps

// ---------------------------------------------------------------------------
// Split-f16 GEMM (3xF16): out[M,128] = epi(A@W + bias), epi = relu [*sc+of].
// 512 thr / 16 warps (4x4 grid, warp tile 32x32), tile 128 rows x 128 cols.
// Full K in smem: ONE sync between staging and a 192-MMA uninterrupted run.
// ---------------------------------------------------------------------------
template <bool DO_BN>
__global__ void __launch_bounds__(512, 1) gemm_f16(
    const float* __restrict__ A, const u16* __restrict__ wsp,
    const float* __restrict__ bias, const float* __restrict__ gam,
    const float* __restrict__ bet, const float* __restrict__ mmean,
    const float* __restrict__ mvar, float* __restrict__ out, int M)
{
    extern __shared__ char sm[];
    const u32 sb = smem_u32(sm);
    float* const bbp = (float*)(sm + SM_BB);
    float* const scp = (float*)(sm + SM_SC);
    float* const ofp = (float*)(sm + SM_OF);

    const int tid = threadIdx.x, wid = tid >> 5, lane = tid & 31;
    const int g = lane >> 2, q = lane & 3;
    const int wm = wid & 3, wn = wid >> 2;       // 4 row x 4 col warp groups
    const int row0 = blockIdx.x * 128;

    if (tid < 128) {
        bbp[tid] = bias[tid];
        float s = 1.f, o = 0.f;
        if (DO_BN) {
            s = gam[tid] * rsqrtf(mvar[tid] + 1e-3f);
            o = bet[tid] - mmean[tid] * s;
        }
        scp[tid] = s;
        ofp[tid] = o;
    }

    // W hi+lo: 64KB via cp.async (no register round-trip).
#pragma unroll
    for (int i = 0; i < 8; i++) {
        int idx = tid + i * 512;                 // 4096 x 16B
        cp16(sb + SM_W + idx * 16, (const char*)wsp + idx * 16);
    }

    // A staging: warp w -> rows w*8..w*8+7; lane j -> float4 col 4j.
    // Split fp32 -> f16 hi/lo, store swizzled.
    {
        const int j4 = lane * 4;                 // col base
        const int ch = lane >> 3;                // k-chunk of this float4
        const int kh = j4 & 31;
#pragma unroll
        for (int i = 0; i < 8; i++) {
            int r = wid * 8 + i;
            int grow = row0 + r;
            float4 v = make_float4(0.f, 0.f, 0.f, 0.f);
            if (grow < M)
                v = *(const float4*)(A + (size_t)grow * HD + j4);
            __half hx = __float2half_rn(v.x), hy = __float2half_rn(v.y),
                   hz = __float2half_rn(v.z), hw = __float2half_rn(v.w);
            union { u16 s[4]; u64 u; } hp, lp;
            hp.s[0] = __half_as_ushort(hx); hp.s[1] = __half_as_ushort(hy);
            hp.s[2] = __half_as_ushort(hz); hp.s[3] = __half_as_ushort(hw);
            lp.s[0] = __half_as_ushort(__float2half_rn(v.x - __half2float(hx)));
            lp.s[1] = __half_as_ushort(__float2half_rn(v.y - __half2float(hy)));
            lp.s[2] = __half_as_ushort(__float2half_rn(v.z - __half2float(hz)));
            lp.s[3] = __half_as_ushort(__float2half_rn(v.w - __half2float(hw)));
            int hidx = swz_idx(r, kh);
            *(u64*)(sm + SM_A + ch * 16384 + hidx * 2) = hp.u;
            *(u64*)(sm + SM_A + ch * 16384 + 8192 + hidx * 2) = lp.u;
        }
    }

    float d[2][4][4];
#pragma unroll
    for (int mt = 0; mt < 2; mt++)
#pragma unroll
        for (int nt = 0; nt < 4; nt++)
#pragma unroll
            for (int c = 0; c < 4; c++) d[mt][nt][c] = 0.f;

    asm volatile("cp.async.commit_group;" ::: "memory");
    asm volatile("cp.async.wait_group 0;" ::: "memory");
    __syncthreads();

    // Mainloop: 4 k-chunks x 2 k16-steps, no syncs.
#pragma unroll
    for (int ch = 0; ch < 4; ++ch) {
        const u32 abase = sb + SM_A + ch * 16384;
        const u32 wbase = sb + SM_W + ch * 8192;
#pragma unroll
        for (int s = 0; s < 2; ++s) {
            u32 fa_hi[2][4], fa_lo[2][4];
            const int ar = wm * 32 + (lane & 7) + ((lane & 8) ? 8 : 0);
            const int aj = s * 2 + ((lane & 16) ? 1 : 0);
#pragma unroll
            for (int mt = 0; mt < 2; mt++) {
                int r = ar + mt * 16;
                u32 off = (u32)(r * 64 + ((aj ^ ((r >> 1) & 3)) << 4));
                ldsm4(fa_hi[mt], abase + off);
                ldsm4(fa_lo[mt], abase + 8192 + off);
            }
            u32 fb_hi[4][2], fb_lo[4][2];
            const int brb = wn * 32 + ((lane & 16) ? 8 : 0) + (lane & 7);
            const int bj = s * 2 + ((lane & 8) ? 1 : 0);
#pragma unroll
            for (int t = 0; t < 2; t++) {
                int r = brb + t * 16;
                u32 off = (u32)(r * 64 + ((bj ^ ((r >> 1) & 3)) << 4));
                u32 tmp[4];
                ldsm4(tmp, wbase + off);
                fb_hi[2 * t][0] = tmp[0]; fb_hi[2 * t][1] = tmp[1];
                fb_hi[2 * t + 1][0] = tmp[2]; fb_hi[2 * t + 1][1] = tmp[3];
                ldsm4(tmp, wbase + 32768 + off);
                fb_lo[2 * t][0] = tmp[0]; fb_lo[2 * t][1] = tmp[1];
                fb_lo[2 * t + 1][0] = tmp[2]; fb_lo[2 * t + 1][1] = tmp[3];
            }
#pragma unroll
            for (int mt = 0; mt < 2; mt++)
#pragma unroll
                for (int nt = 0; nt < 4; nt++)
                    mma_f16(d[mt][nt], fa_hi[mt], fb_hi[nt]);
#pragma unroll
            for (int mt = 0; mt < 2; mt++)
#pragma unroll
                for (int nt = 0; nt < 4; nt++)
                    mma_f16(d[mt][nt], fa_hi[mt], fb_lo[nt]);
#pragma unroll
            for (int mt = 0; mt < 2; mt++)
#pragma unroll
                for (int nt = 0; nt < 4; nt++)
                    mma_f16(d[mt][nt], fa_lo[mt], fb_hi[nt]);
        }
    }

    // Epilogue
    const int q2 = q * 2;
#pragma unroll
    for (int mt = 0; mt < 2; mt++) {
        int r0 = row0 + wm * 32 + mt * 16 + g;
#pragma unroll
        for (int nt = 0; nt < 4; nt++) {
            int col = wn * 32 + nt * 8 + q2;
            float s0 = scp[col], s1 = scp[col + 1];
            float o0 = ofp[col], o1 = ofp[col + 1];
            float B0 = bbp[col], B1 = bbp[col + 1];
            float v0 = fmaxf(d[mt][nt][0] + B0, 0.f) * s0 + o0;
            float v1 = fmaxf(d[mt][nt][1] + B1, 0.f) * s1 + o1;
            float v2 = fmaxf(d[mt][nt][2] + B0, 0.f) * s0 + o0;
            float v3 = fmaxf(d[mt][nt][3] + B1, 0.f) * s1 + o1;
            if (r0 < M)
                *(float2*)(out + (size_t)r0 * HD + col) = make_float2(v0, v1);
            if (r0 + 8 < M)
                *(float2*)(out + (size_t)(r0 + 8) * HD + col) = make_float2(v2, v3);
        }
    }
}

// ---------------------------------------------------------------------------
// Final graph readout: sorted batch -> chunked register accumulation.
// ---------------------------------------------------------------------------
#define SEG_CH 64
__global__ void seg_sum(const float* __restrict__ h,
                        const int* __restrict__ batch,
                        float* __restrict__ out)
{
    int n0 = blockIdx.x * SEG_CH;
    if (n0 >= NN) return;
    int j = threadIdx.x;
    int nend = n0 + SEG_CH;
    if (nend > NN) nend = NN;
    float acc = 0.f;
    int cur = __ldg(batch + n0);
    for (int n = n0; n < nend; ++n) {
        int b = __ldg(batch + n);
        if (b != cur) {
            atomicAdd(out + (size_t)cur * HD + j, acc);
            acc = 0.f;
            cur = b;
        }
        acc += __ldg(h + (size_t)n * HD + j);
    }
    atomicAdd(out + (size_t)cur * HD + j, acc);
}

__global__ void zero_out(float* __restrict__ out, int n)
{
    int t = blockIdx.x * blockDim.x + threadIdx.x;
    if (t < n) out[t] = 0.f;
}

extern "C" void kernel_launch(void* const* d_in, const int* in_sizes, int n_in,
                              void* d_out, int out_size)
{
    const float* x   = (const float*)d_in[0];
    const int*   ei  = (const int*)d_in[1];
    const int*   bat = (const int*)d_in[2];
    const float* W1  = (const float*)d_in[3];
    const float* b1  = (const float*)d_in[4];
    const float* g1  = (const float*)d_in[5];
    const float* be1 = (const float*)d_in[6];
    const float* mm1 = (const float*)d_in[7];
    const float* mv1 = (const float*)d_in[8];
    const float* W2  = (const float*)d_in[9];
    const float* b2  = (const float*)d_in[10];
    const float* W3  = (const float*)d_in[11];
    const float* b3  = (const float*)d_in[12];
    const float* g2  = (const float*)d_in[13];
    const float* be2 = (const float*)d_in[14];
    const float* mm2 = (const float*)d_in[15];
    const float* mv2 = (const float*)d_in[16];
    const float* W4  = (const float*)d_in[17];
    const float* b4  = (const float*)d_in[18];
    float* out = (float*)d_out;

    float *bufA, *bufB, *bufC;
    u16* wsp;
    int *rp, *cur, *ssrc, *bsum;
    cudaGetSymbolAddress((void**)&bufA, g_bufA);
    cudaGetSymbolAddress((void**)&bufB, g_bufB);
    cudaGetSymbolAddress((void**)&bufC, g_bufC);
    cudaGetSymbolAddress((void**)&wsp, g_wsp);
    cudaGetSymbolAddress((void**)&rp, g_rp);
    cudaGetSymbolAddress((void**)&cur, g_cur);
    cudaGetSymbolAddress((void**)&ssrc, g_ssrc);
    cudaGetSymbolAddress((void**)&bsum, g_bsum);

    cudaFuncSetAttribute(gemm_f16<true>,
                         cudaFuncAttributeMaxDynamicSharedMemorySize, SM_TOT);
    cudaFuncSetAttribute(gemm_f16<false>,
                         cudaFuncAttributeMaxDynamicSharedMemorySize, SM_TOT);

    const int gemm_blocks = (NN + 127) / 128;          // 391
    const int edge_blocks = (EE + 255) / 256;          // 2500
    const int agg_blocks  = (NN * 32 + 255) / 256;     // 6250
    const int seg_blocks  = (NN + SEG_CH - 1) / SEG_CH;

    // W prep + CSR build
    prep_w<<<256, 256>>>(W1, W2, W3, W4, wsp);
    csr_zero<<<(NN + 255) / 256, 256>>>(cur);
    csr_hist<<<edge_blocks, 256>>>(ei, cur);
    csr_scan1<<<SCAN_B, 256>>>(cur, bsum);
    csr_scan2<<<1, 32>>>(bsum, rp);
    csr_scan3<<<SCAN_B, 256>>>(cur, bsum, rp, cur);
    csr_place<<<edge_blocks, 256>>>(ei, cur, ssrc);

    // h = bn1(relu(x@W1+b1))
    gemm_f16<true><<<gemm_blocks, 512, SM_TOT>>>(
        x, wsp + 0 * 32768, b1, g1, be1, mm1, mv1, bufA, NN);
    // h = relu(h@W2+b2)
    gemm_f16<false><<<gemm_blocks, 512, SM_TOT>>>(
        bufA, wsp + 1 * 32768, b2, nullptr, nullptr, nullptr, nullptr, bufB, NN);
    // bufC = bufB + aggregate(bufB)
    csr_agg<<<agg_blocks, 256>>>(bufB, rp, ssrc, bufC);
    // h = bn2(relu(bufC@W3+b3))
    gemm_f16<true><<<gemm_blocks, 512, SM_TOT>>>(
        bufC, wsp + 2 * 32768, b3, g2, be2, mm2, mv2, bufA, NN);
    // bufB = bufA + aggregate(bufA)
    csr_agg<<<agg_blocks, 256>>>(bufA, rp, ssrc, bufB);
    // h = relu(bufB@W4+b4)
    gemm_f16<false><<<gemm_blocks, 512, SM_TOT>>>(
        bufB, wsp + 3 * 32768, b4, nullptr, nullptr, nullptr, nullptr, bufA, NN);
    // out = segment_sum(h, batch)
    zero_out<<<(GG * HD + 255) / 256, 256>>>(out, GG * HD);
    seg_sum<<<seg_blocks, 128>>>(bufA, bat, out);
}

// round 9
// speedup vs baseline: 2.4259x; 1.1022x over previous
#include <cuda_runtime.h>
#include <cuda_fp16.h>

#define NN 50000
#define HD 128
#define EE 640000
#define GG 128

typedef unsigned int u32;
typedef unsigned short u16;
typedef unsigned long long u64;

// Scratch buffers
__device__ float g_bufA[NN * HD];
__device__ float g_bufB[NN * HD];
__device__ float g_bufC[NN * HD];
// Pre-split W: [layer][hi/lo][16384 halves], swizzled smem image.
__device__ __align__(16) u16 g_wsp[4 * 2 * 16384];
// CSR-by-dst scratch
__device__ int g_rp[NN + 1];
__device__ int g_cur[NN];
__device__ int g_ssrc[EE];
__device__ int g_bsum[256];

#define SCAN_B 196

__device__ __forceinline__ u32 smem_u32(const void* p) {
    u32 a;
    asm("{ .reg .u64 t; cvta.to.shared.u64 t, %1; cvt.u32.u64 %0, t; }"
        : "=r"(a) : "l"(p));
    return a;
}
__device__ __forceinline__ void mma_f16(float* d, const u32* a, const u32* b) {
    asm("mma.sync.aligned.m16n8k16.row.col.f32.f16.f16.f32 "
        "{%0,%1,%2,%3}, {%4,%5,%6,%7}, {%8,%9}, {%0,%1,%2,%3};"
        : "+f"(d[0]), "+f"(d[1]), "+f"(d[2]), "+f"(d[3])
        : "r"(a[0]), "r"(a[1]), "r"(a[2]), "r"(a[3]), "r"(b[0]), "r"(b[1]));
}
__device__ __forceinline__ void ldsm4(u32* r, u32 addr) {
    asm volatile("ldmatrix.sync.aligned.m8n8.x4.shared.b16 {%0,%1,%2,%3}, [%4];"
                 : "=r"(r[0]), "=r"(r[1]), "=r"(r[2]), "=r"(r[3]) : "r"(addr));
}
__device__ __forceinline__ void cp16(u32 smem, const void* g) {
    asm volatile("cp.async.cg.shared.global [%0], [%1], 16;"
                 :: "r"(smem), "l"(g) : "memory");
}
__device__ __forceinline__ int swz_idx(int r, int kh) {
    return r * 32 + ((((kh >> 3) ^ ((r >> 1) & 3)) << 3) | (kh & 7));
}

// ---------------------------------------------------------------------------
// W prep: f16 hi/lo split, transposed [n][k], k-chunked, swizzled.
// ---------------------------------------------------------------------------
__global__ void prep_w(const float* __restrict__ W1, const float* __restrict__ W2,
                       const float* __restrict__ W3, const float* __restrict__ W4,
                       u16* __restrict__ out)
{
    int t = blockIdx.x * 256 + threadIdx.x;
    int layer = t >> 14, e = t & 16383;
    int k = e >> 7, n = e & 127;
    const float* W = layer == 0 ? W1 : layer == 1 ? W2 : layer == 2 ? W3 : W4;
    float v = W[k * HD + n];
    __half hi = __float2half_rn(v);
    __half lo = __float2half_rn(v - __half2float(hi));
    int ch = k >> 5, kh = k & 31;
    int idx = ch * 4096 + swz_idx(n, kh);
    int base = layer * 32768;
    out[base + idx]         = __half_as_ushort(hi);
    out[base + 16384 + idx] = __half_as_ushort(lo);
}

// ---------------------------------------------------------------------------
// CSR build
// ---------------------------------------------------------------------------
__global__ void csr_zero(int* __restrict__ cnt)
{
    int t = blockIdx.x * blockDim.x + threadIdx.x;
    if (t < NN) cnt[t] = 0;
}
__global__ void csr_hist(const int* __restrict__ ei, int* __restrict__ cnt)
{
    int e = blockIdx.x * blockDim.x + threadIdx.x;
    if (e < EE) atomicAdd(cnt + __ldg(ei + 2 * e + 1), 1);
}
__global__ void csr_scan1(const int* __restrict__ cnt, int* __restrict__ bsum)
{
    __shared__ int s[256];
    int t = threadIdx.x, i = blockIdx.x * 256 + t;
    s[t] = (i < NN) ? cnt[i] : 0;
    __syncthreads();
    for (int o = 128; o > 0; o >>= 1) {
        if (t < o) s[t] += s[t + o];
        __syncthreads();
    }
    if (t == 0) bsum[blockIdx.x] = s[0];
}
__global__ void csr_scan2(int* __restrict__ bsum, int* __restrict__ rp)
{
    if (threadIdx.x == 0) {
        int run = 0;
        for (int b = 0; b < SCAN_B; b++) {
            int v = bsum[b];
            bsum[b] = run;
            run += v;
        }
        rp[NN] = run;
    }
}
__global__ void csr_scan3(const int* __restrict__ cnt, const int* __restrict__ bsum,
                          int* __restrict__ rp, int* __restrict__ cur)
{
    __shared__ int s[256];
    int t = threadIdx.x, i = blockIdx.x * 256 + t;
    int c = (i < NN) ? cnt[i] : 0;
    s[t] = c;
    __syncthreads();
    for (int o = 1; o < 256; o <<= 1) {
        int v = (t >= o) ? s[t - o] : 0;
        __syncthreads();
        s[t] += v;
        __syncthreads();
    }
    if (i < NN) {
        int excl = bsum[blockIdx.x] + s[t] - c;
        rp[i] = excl;
        cur[i] = excl;
    }
}
__global__ void csr_place(const int* __restrict__ ei, int* __restrict__ cur,
                          int* __restrict__ ssrc)
{
    int e = blockIdx.x * blockDim.x + threadIdx.x;
    if (e >= EE) return;
    int src = __ldg(ei + 2 * e);
    int dst = __ldg(ei + 2 * e + 1);
    int pos = atomicAdd(cur + dst, 1);
    ssrc[pos] = src;
}

// ---------------------------------------------------------------------------
// Atomic-free aggregate: out[d,:] = h[d,:] + sum_{e in row d} h[ssrc[e],:]
// One warp per dst; 4-wide edge unroll -> 4 independent gathers in flight.
// ---------------------------------------------------------------------------
__global__ void __launch_bounds__(256) csr_agg(
    const float* __restrict__ h, const int* __restrict__ rp,
    const int* __restrict__ ssrc, float* __restrict__ out)
{
    int d = (blockIdx.x * blockDim.x + threadIdx.x) >> 5;
    if (d >= NN) return;
    int lane = threadIdx.x & 31;
    float4 acc = __ldg((const float4*)(h + (size_t)d * HD) + lane);
    int e = __ldg(rp + d), e1 = __ldg(rp + d + 1);
    for (; e + 4 <= e1; e += 4) {
        int s0 = __ldg(ssrc + e + 0);
        int s1 = __ldg(ssrc + e + 1);
        int s2 = __ldg(ssrc + e + 2);
        int s3 = __ldg(ssrc + e + 3);
        float4 v0 = __ldg((const float4*)(h + (size_t)s0 * HD) + lane);
        float4 v1 = __ldg((const float4*)(h + (size_t)s1 * HD) + lane);
        float4 v2 = __ldg((const float4*)(h + (size_t)s2 * HD) + lane);
        float4 v3 = __ldg((const float4*)(h + (size_t)s3 * HD) + lane);
        acc.x += (v0.x + v1.x) + (v2.x + v3.x);
        acc.y += (v0.y + v1.y) + (v2.y + v3.y);
        acc.z += (v0.z + v1.z) + (v2.z + v3.z);
        acc.w += (v0.w + v1.w) + (v2.w + v3.w);
    }
    for (; e < e1; ++e) {
        int s = __ldg(ssrc + e);
        float4 v = __ldg((const float4*)(h + (size_t)s * HD) + lane);
        acc.x += v.x; acc.y += v.y; acc.z += v.z; acc.w += v.w;
    }
    *((float4*)(out + (size_t)d * HD) + lane) = acc;
}

// ---------------------------------------------------------------------------
// Smem layout (bytes). Full-K resident.
// ---------------------------------------------------------------------------
#define SM_BB  0
#define SM_SC  512
#define SM_OF  1024
#define SM_W   1536
#define SM_A   (SM_W + 65536)
#define SM_TOT (SM_A + 65536)            // 132608 B -> 1 CTA/SM, 16 warps

// ---------------------------------------------------------------------------
// Split-f16 GEMM (3xF16): out[M,128] = epi(A@W + bias), epi = relu [*sc+of].
// ---------------------------------------------------------------------------
template <bool DO_BN>
__global__ void __launch_bounds__(512, 1) gemm_f16(
    const float* __restrict__ A, const u16* __restrict__ wsp,
    const float* __restrict__ bias, const float* __restrict__ gam,
    const float* __restrict__ bet, const float* __restrict__ mmean,
    const float* __restrict__ mvar, float* __restrict__ out, int M)
{
    extern __shared__ char sm[];
    const u32 sb = smem_u32(sm);
    float* const bbp = (float*)(sm + SM_BB);
    float* const scp = (float*)(sm + SM_SC);
    float* const ofp = (float*)(sm + SM_OF);

    const int tid = threadIdx.x, wid = tid >> 5, lane = tid & 31;
    const int g = lane >> 2, q = lane & 3;
    const int wm = wid & 3, wn = wid >> 2;
    const int row0 = blockIdx.x * 128;

    if (tid < 128) {
        bbp[tid] = bias[tid];
        float s = 1.f, o = 0.f;
        if (DO_BN) {
            s = gam[tid] * rsqrtf(mvar[tid] + 1e-3f);
            o = bet[tid] - mmean[tid] * s;
        }
        scp[tid] = s;
        ofp[tid] = o;
    }

#pragma unroll
    for (int i = 0; i < 8; i++) {
        int idx = tid + i * 512;
        cp16(sb + SM_W + idx * 16, (const char*)wsp + idx * 16);
    }

    {
        const int j4 = lane * 4;
        const int ch = lane >> 3;
        const int kh = j4 & 31;
#pragma unroll
        for (int i = 0; i < 8; i++) {
            int r = wid * 8 + i;
            int grow = row0 + r;
            float4 v = make_float4(0.f, 0.f, 0.f, 0.f);
            if (grow < M)
                v = *(const float4*)(A + (size_t)grow * HD + j4);
            __half hx = __float2half_rn(v.x), hy = __float2half_rn(v.y),
                   hz = __float2half_rn(v.z), hw = __float2half_rn(v.w);
            union { u16 s[4]; u64 u; } hp, lp;
            hp.s[0] = __half_as_ushort(hx); hp.s[1] = __half_as_ushort(hy);
            hp.s[2] = __half_as_ushort(hz); hp.s[3] = __half_as_ushort(hw);
            lp.s[0] = __half_as_ushort(__float2half_rn(v.x - __half2float(hx)));
            lp.s[1] = __half_as_ushort(__float2half_rn(v.y - __half2float(hy)));
            lp.s[2] = __half_as_ushort(__float2half_rn(v.z - __half2float(hz)));
            lp.s[3] = __half_as_ushort(__float2half_rn(v.w - __half2float(hw)));
            int hidx = swz_idx(r, kh);
            *(u64*)(sm + SM_A + ch * 16384 + hidx * 2) = hp.u;
            *(u64*)(sm + SM_A + ch * 16384 + 8192 + hidx * 2) = lp.u;
        }
    }

    float d[2][4][4];
#pragma unroll
    for (int mt = 0; mt < 2; mt++)
#pragma unroll
        for (int nt = 0; nt < 4; nt++)
#pragma unroll
            for (int c = 0; c < 4; c++) d[mt][nt][c] = 0.f;

    asm volatile("cp.async.commit_group;" ::: "memory");
    asm volatile("cp.async.wait_group 0;" ::: "memory");
    __syncthreads();

#pragma unroll
    for (int ch = 0; ch < 4; ++ch) {
        const u32 abase = sb + SM_A + ch * 16384;
        const u32 wbase = sb + SM_W + ch * 8192;
#pragma unroll
        for (int s = 0; s < 2; ++s) {
            u32 fa_hi[2][4], fa_lo[2][4];
            const int ar = wm * 32 + (lane & 7) + ((lane & 8) ? 8 : 0);
            const int aj = s * 2 + ((lane & 16) ? 1 : 0);
#pragma unroll
            for (int mt = 0; mt < 2; mt++) {
                int r = ar + mt * 16;
                u32 off = (u32)(r * 64 + ((aj ^ ((r >> 1) & 3)) << 4));
                ldsm4(fa_hi[mt], abase + off);
                ldsm4(fa_lo[mt], abase + 8192 + off);
            }
            u32 fb_hi[4][2], fb_lo[4][2];
            const int brb = wn * 32 + ((lane & 16) ? 8 : 0) + (lane & 7);
            const int bj = s * 2 + ((lane & 8) ? 1 : 0);
#pragma unroll
            for (int t = 0; t < 2; t++) {
                int r = brb + t * 16;
                u32 off = (u32)(r * 64 + ((bj ^ ((r >> 1) & 3)) << 4));
                u32 tmp[4];
                ldsm4(tmp, wbase + off);
                fb_hi[2 * t][0] = tmp[0]; fb_hi[2 * t][1] = tmp[1];
                fb_hi[2 * t + 1][0] = tmp[2]; fb_hi[2 * t + 1][1] = tmp[3];
                ldsm4(tmp, wbase + 32768 + off);
                fb_lo[2 * t][0] = tmp[0]; fb_lo[2 * t][1] = tmp[1];
                fb_lo[2 * t + 1][0] = tmp[2]; fb_lo[2 * t + 1][1] = tmp[3];
            }
#pragma unroll
            for (int mt = 0; mt < 2; mt++)
#pragma unroll
                for (int nt = 0; nt < 4; nt++)
                    mma_f16(d[mt][nt], fa_hi[mt], fb_hi[nt]);
#pragma unroll
            for (int mt = 0; mt < 2; mt++)
#pragma unroll
                for (int nt = 0; nt < 4; nt++)
                    mma_f16(d[mt][nt], fa_hi[mt], fb_lo[nt]);
#pragma unroll
            for (int mt = 0; mt < 2; mt++)
#pragma unroll
                for (int nt = 0; nt < 4; nt++)
                    mma_f16(d[mt][nt], fa_lo[mt], fb_hi[nt]);
        }
    }

    const int q2 = q * 2;
#pragma unroll
    for (int mt = 0; mt < 2; mt++) {
        int r0 = row0 + wm * 32 + mt * 16 + g;
#pragma unroll
        for (int nt = 0; nt < 4; nt++) {
            int col = wn * 32 + nt * 8 + q2;
            float s0 = scp[col], s1 = scp[col + 1];
            float o0 = ofp[col], o1 = ofp[col + 1];
            float B0 = bbp[col], B1 = bbp[col + 1];
            float v0 = fmaxf(d[mt][nt][0] + B0, 0.f) * s0 + o0;
            float v1 = fmaxf(d[mt][nt][1] + B1, 0.f) * s1 + o1;
            float v2 = fmaxf(d[mt][nt][2] + B0, 0.f) * s0 + o0;
            float v3 = fmaxf(d[mt][nt][3] + B1, 0.f) * s1 + o1;
            if (r0 < M)
                *(float2*)(out + (size_t)r0 * HD + col) = make_float2(v0, v1);
            if (r0 + 8 < M)
                *(float2*)(out + (size_t)(r0 + 8) * HD + col) = make_float2(v2, v3);
        }
    }
}

// ---------------------------------------------------------------------------
// Final graph readout: sorted batch -> chunked register accumulation.
// ---------------------------------------------------------------------------
#define SEG_CH 64
__global__ void seg_sum(const float* __restrict__ h,
                        const int* __restrict__ batch,
                        float* __restrict__ out)
{
    int n0 = blockIdx.x * SEG_CH;
    if (n0 >= NN) return;
    int j = threadIdx.x;
    int nend = n0 + SEG_CH;
    if (nend > NN) nend = NN;
    float acc = 0.f;
    int cur = __ldg(batch + n0);
    for (int n = n0; n < nend; ++n) {
        int b = __ldg(batch + n);
        if (b != cur) {
            atomicAdd(out + (size_t)cur * HD + j, acc);
            acc = 0.f;
            cur = b;
        }
        acc += __ldg(h + (size_t)n * HD + j);
    }
    atomicAdd(out + (size_t)cur * HD + j, acc);
}

__global__ void zero_out(float* __restrict__ out, int n)
{
    int t = blockIdx.x * blockDim.x + threadIdx.x;
    if (t < n) out[t] = 0.f;
}

extern "C" void kernel_launch(void* const* d_in, const int* in_sizes, int n_in,
                              void* d_out, int out_size)
{
    const float* x   = (const float*)d_in[0];
    const int*   ei  = (const int*)d_in[1];
    const int*   bat = (const int*)d_in[2];
    const float* W1  = (const float*)d_in[3];
    const float* b1  = (const float*)d_in[4];
    const float* g1  = (const float*)d_in[5];
    const float* be1 = (const float*)d_in[6];
    const float* mm1 = (const float*)d_in[7];
    const float* mv1 = (const float*)d_in[8];
    const float* W2  = (const float*)d_in[9];
    const float* b2  = (const float*)d_in[10];
    const float* W3  = (const float*)d_in[11];
    const float* b3  = (const float*)d_in[12];
    const float* g2  = (const float*)d_in[13];
    const float* be2 = (const float*)d_in[14];
    const float* mm2 = (const float*)d_in[15];
    const float* mv2 = (const float*)d_in[16];
    const float* W4  = (const float*)d_in[17];
    const float* b4  = (const float*)d_in[18];
    float* out = (float*)d_out;

    float *bufA, *bufB, *bufC;
    u16* wsp;
    int *rp, *cur, *ssrc, *bsum;
    cudaGetSymbolAddress((void**)&bufA, g_bufA);
    cudaGetSymbolAddress((void**)&bufB, g_bufB);
    cudaGetSymbolAddress((void**)&bufC, g_bufC);
    cudaGetSymbolAddress((void**)&wsp, g_wsp);
    cudaGetSymbolAddress((void**)&rp, g_rp);
    cudaGetSymbolAddress((void**)&cur, g_cur);
    cudaGetSymbolAddress((void**)&ssrc, g_ssrc);
    cudaGetSymbolAddress((void**)&bsum, g_bsum);

    cudaFuncSetAttribute(gemm_f16<true>,
                         cudaFuncAttributeMaxDynamicSharedMemorySize, SM_TOT);
    cudaFuncSetAttribute(gemm_f16<false>,
                         cudaFuncAttributeMaxDynamicSharedMemorySize, SM_TOT);

    // Side stream + events for capture-time fork (host objects, created once;
    // identical device work every call).
    static cudaStream_t s2 = nullptr;
    static cudaEvent_t evFork = nullptr, evJoin = nullptr;
    if (s2 == nullptr) {
        cudaStreamCreateWithFlags(&s2, cudaStreamNonBlocking);
        cudaEventCreateWithFlags(&evFork, cudaEventDisableTiming);
        cudaEventCreateWithFlags(&evJoin, cudaEventDisableTiming);
    }

    const int gemm_blocks = (NN + 127) / 128;          // 391
    const int edge_blocks = (EE + 255) / 256;          // 2500
    const int agg_blocks  = (NN * 32 + 255) / 256;     // 6250
    const int seg_blocks  = (NN + SEG_CH - 1) / SEG_CH;

    // Main stream: W prep (GEMM dependency) first.
    prep_w<<<256, 256>>>(W1, W2, W3, W4, wsp);

    // Fork: CSR build + output zeroing run concurrently with GEMM1/GEMM2.
    cudaEventRecord(evFork, 0);
    cudaStreamWaitEvent(s2, evFork, 0);
    csr_zero<<<(NN + 255) / 256, 256, 0, s2>>>(cur);
    csr_hist<<<edge_blocks, 256, 0, s2>>>(ei, cur);
    csr_scan1<<<SCAN_B, 256, 0, s2>>>(cur, bsum);
    csr_scan2<<<1, 32, 0, s2>>>(bsum, rp);
    csr_scan3<<<SCAN_B, 256, 0, s2>>>(cur, bsum, rp, cur);
    csr_place<<<edge_blocks, 256, 0, s2>>>(ei, cur, ssrc);
    zero_out<<<(GG * HD + 255) / 256, 256, 0, s2>>>(out, GG * HD);
    cudaEventRecord(evJoin, s2);

    // h = bn1(relu(x@W1+b1))
    gemm_f16<true><<<gemm_blocks, 512, SM_TOT>>>(
        x, wsp + 0 * 32768, b1, g1, be1, mm1, mv1, bufA, NN);
    // h = relu(h@W2+b2)
    gemm_f16<false><<<gemm_blocks, 512, SM_TOT>>>(
        bufA, wsp + 1 * 32768, b2, nullptr, nullptr, nullptr, nullptr, bufB, NN);

    // Join: csr_agg needs the CSR arrays.
    cudaStreamWaitEvent(0, evJoin, 0);

    // bufC = bufB + aggregate(bufB)
    csr_agg<<<agg_blocks, 256>>>(bufB, rp, ssrc, bufC);
    // h = bn2(relu(bufC@W3+b3))
    gemm_f16<true><<<gemm_blocks, 512, SM_TOT>>>(
        bufC, wsp + 2 * 32768, b3, g2, be2, mm2, mv2, bufA, NN);
    // bufB = bufA + aggregate(bufA)
    csr_agg<<<agg_blocks, 256>>>(bufA, rp, ssrc, bufB);
    // h = relu(bufB@W4+b4)
    gemm_f16<false><<<gemm_blocks, 512, SM_TOT>>>(
        bufB, wsp + 3 * 32768, b4, nullptr, nullptr, nullptr, nullptr, bufA, NN);
    // out = segment_sum(h, batch)
    seg_sum<<<seg_blocks, 128>>>(bufA, bat, out);
}